// round 6
// baseline (speedup 1.0000x reference)
#include <cuda_runtime.h>
#include <math.h>
#include <stdint.h>

// Problem dims
#define Bb   64
#define Tt   2048
#define INx  64
#define Hh   512
#define OUTD 32
#define K1   576      // INx + Hh
#define NCTA1 132     // 132*8 = 1056 = 1024 fz cols + 32 y cols
#define NC1  8        // phase-1 cols per CTA
#define NCTA2 128     // 128*4 = 512 r cols
#define NC2  4        // phase-2 cols per CTA
#define NTHR 512      // m = tid & 63, ks = tid >> 6 (8 K-slices)

// ---- persistent device scratch (no allocation allowed) ----
__device__ float g_xT [Hh * Bb];               // state, transposed [k][m]
__device__ float g_xfT[Hh * Bb];               // f*x, transposed  [k][m]
__device__ float g_z  [Hh * Bb];               // z gate           [j][m]
__device__ float g_uT [(size_t)Tt * INx * Bb]; // u transposed: [t][i][m]  (32 MB)
__device__ unsigned g_bar;

// Hardened grid barrier:
//  - EVERY thread executes __threadfence() (fence.sc.gpu -> store-queue drain +
//    L1D CCTL.IVALL in every SM) on both release and acquire sides.
//  - arrival/spin via strong atomics only (no weak ld.cg polling).
//  - monotonic counter, co-residency guaranteed by cooperative launch.
__device__ __forceinline__ void grid_barrier(unsigned target) {
  __threadfence();                    // release: per-SM drain/flush, all threads
  __syncthreads();
  if (threadIdx.x == 0) {
    atomicAdd(&g_bar, 1u);
    while (atomicAdd(&g_bar, 0u) < target) { }
  }
  __syncthreads();
  __threadfence();                    // acquire: flush L1 before post-barrier loads
}

__global__ void __launch_bounds__(NTHR, 1) gru_main(
    const float* __restrict__ kernel_fz, const float* __restrict__ bias_fz,
    const float* __restrict__ kernel_r,  const float* __restrict__ bias_r,
    const float* __restrict__ W_out,     const float* __restrict__ b_out,
    float* __restrict__ out)
{
  __shared__ __align__(16) float s_w1[K1 * NC1];  // [kk][n], kk 0..511=x rows, 512..575=u rows
  __shared__ __align__(16) float s_w2[K1 * NC2];
  __shared__ float s_red[NTHR * NC1];
  __shared__ float s_b1[NC1];
  __shared__ float s_b2[NC2];

  const int tid = threadIdx.x;
  const int cid = blockIdx.x;
  const int m   = tid & 63;   // batch row
  const int ks  = tid >> 6;   // K-slice 0..7

  // ---- stationary weight slices into SMEM (once) ----
  for (int i = tid; i < K1 * NC1; i += NTHR) {
    int kk = i / NC1, n = i % NC1;
    int c  = cid * NC1 + n;
    int row = (kk < Hh) ? (INx + kk) : (kk - Hh);   // concat order: [u | x]
    float w;
    if (c < 2 * Hh) w = kernel_fz[row * (2 * Hh) + c];
    else { int o = c - 2 * Hh; w = (kk < Hh) ? W_out[o * Hh + kk] : 0.0f; }
    s_w1[i] = w;
  }
  if (cid < NCTA2) {
    for (int i = tid; i < K1 * NC2; i += NTHR) {
      int kk = i / NC2, n = i % NC2;
      int j  = cid * NC2 + n;
      int row = (kk < Hh) ? (INx + kk) : (kk - Hh);
      s_w2[i] = kernel_r[row * Hh + j];
    }
  }
  if (tid < NC1) {
    int c = cid * NC1 + tid;
    s_b1[tid] = (c < 2 * Hh) ? bias_fz[c] : b_out[c - 2 * Hh];
  }
  if (cid < NCTA2 && tid < NC2) s_b2[tid] = bias_r[cid * NC2 + tid];
  __syncthreads();

  unsigned target = 0;
  for (int t = 0; t < Tt; t++) {
    const float* uT_t = g_uT + (size_t)t * (INx * Bb);

    // ================= phase 1: fz logits + y readout =================
    {
      float acc[NC1];
      #pragma unroll
      for (int n = 0; n < NC1; n++) acc[n] = 0.0f;

      { // x segment: rows [ks*64, ks*64+64)
        const float* xp = g_xT + (ks * 64) * Bb + m;
        const float* wp = s_w1 + (ks * 64) * NC1;
        #pragma unroll 8
        for (int k = 0; k < 64; k++) {
          float xv = xp[k * Bb];
          const float4* w4 = (const float4*)(wp + k * NC1);
          float4 wa = w4[0], wb = w4[1];
          acc[0] = fmaf(xv, wa.x, acc[0]);
          acc[1] = fmaf(xv, wa.y, acc[1]);
          acc[2] = fmaf(xv, wa.z, acc[2]);
          acc[3] = fmaf(xv, wa.w, acc[3]);
          acc[4] = fmaf(xv, wb.x, acc[4]);
          acc[5] = fmaf(xv, wb.y, acc[5]);
          acc[6] = fmaf(xv, wb.z, acc[6]);
          acc[7] = fmaf(xv, wb.w, acc[7]);
        }
      }
      { // u segment: rows [512 + ks*8, 512 + ks*8 + 8)
        const float* up = uT_t + (ks * 8) * Bb + m;
        const float* wp = s_w1 + (Hh + ks * 8) * NC1;
        #pragma unroll
        for (int k = 0; k < 8; k++) {
          float uv = up[k * Bb];
          const float4* w4 = (const float4*)(wp + k * NC1);
          float4 wa = w4[0], wb = w4[1];
          acc[0] = fmaf(uv, wa.x, acc[0]);
          acc[1] = fmaf(uv, wa.y, acc[1]);
          acc[2] = fmaf(uv, wa.z, acc[2]);
          acc[3] = fmaf(uv, wa.w, acc[3]);
          acc[4] = fmaf(uv, wb.x, acc[4]);
          acc[5] = fmaf(uv, wb.y, acc[5]);
          acc[6] = fmaf(uv, wb.z, acc[6]);
          acc[7] = fmaf(uv, wb.w, acc[7]);
        }
      }
      #pragma unroll
      for (int n = 0; n < NC1; n++) s_red[tid * NC1 + n] = acc[n];
      __syncthreads();

      { // epilogue: 512 threads -> 64 batch x 8 cols
        int mm = tid & 63, n = tid >> 6;
        float s = s_b1[n];
        #pragma unroll
        for (int q = 0; q < 8; q++) s += s_red[(q * 64 + mm) * NC1 + n];
        int c = cid * NC1 + n;
        if (c < Hh) {                                  // f gate -> f*x
          float f  = 1.0f / (1.0f + expf(-s));
          g_xfT[c * Bb + mm] = f * g_xT[c * Bb + mm];
        } else if (c < 2 * Hh) {                       // z gate
          g_z[(c - Hh) * Bb + mm] = 1.0f / (1.0f + expf(-s));
        } else {                                       // y readout (pre-update x)
          out[((size_t)mm * Tt + t) * OUTD + (c - 2 * Hh)] = s;
        }
      }
    }
    target += NCTA1;
    grid_barrier(target);

    // ================= phase 2: r + state update =================
    if (cid < NCTA2) {
      float acc[NC2];
      #pragma unroll
      for (int n = 0; n < NC2; n++) acc[n] = 0.0f;

      {
        const float* xp = g_xfT + (ks * 64) * Bb + m;
        const float* wp = s_w2 + (ks * 64) * NC2;
        #pragma unroll 8
        for (int k = 0; k < 64; k++) {
          float xv = xp[k * Bb];
          float4 wa = *(const float4*)(wp + k * NC2);
          acc[0] = fmaf(xv, wa.x, acc[0]);
          acc[1] = fmaf(xv, wa.y, acc[1]);
          acc[2] = fmaf(xv, wa.z, acc[2]);
          acc[3] = fmaf(xv, wa.w, acc[3]);
        }
      }
      {
        const float* up = uT_t + (ks * 8) * Bb + m;
        const float* wp = s_w2 + (Hh + ks * 8) * NC2;
        #pragma unroll
        for (int k = 0; k < 8; k++) {
          float uv = up[k * Bb];
          float4 wa = *(const float4*)(wp + k * NC2);
          acc[0] = fmaf(uv, wa.x, acc[0]);
          acc[1] = fmaf(uv, wa.y, acc[1]);
          acc[2] = fmaf(uv, wa.z, acc[2]);
          acc[3] = fmaf(uv, wa.w, acc[3]);
        }
      }
      #pragma unroll
      for (int n = 0; n < NC2; n++) s_red[tid * NC2 + n] = acc[n];
      __syncthreads();

      if (tid < 256) {                  // 64 batch x 4 cols
        int mm = tid & 63, n = tid >> 6;
        float s = s_b2[n];
        #pragma unroll
        for (int q = 0; q < 8; q++) s += s_red[(q * 64 + mm) * NC2 + n];
        int c = cid * NC2 + n;
        float r  = tanhf(s);
        float z  = g_z[c * Bb + mm];
        float xo = g_xT[c * Bb + mm];
        g_xT[c * Bb + mm] = (1.0f - z) * xo + z * r;
      }
    }
    target += NCTA1;
    grid_barrier(target);
  }
}

// ===================== round-5 fallback kernels (diagnostic path) =====================
__global__ void __launch_bounds__(NTHR, 1) phase1_kernel(
    const float* __restrict__ kernel_fz, const float* __restrict__ bias_fz,
    const float* __restrict__ W_out,     const float* __restrict__ b_out,
    float* __restrict__ out, int t)
{
  __shared__ __align__(16) float s_w1[K1 * NC1];
  __shared__ float s_red[NTHR * NC1];
  __shared__ float s_b1[NC1];
  const int tid = threadIdx.x, cid = blockIdx.x;
  const int m = tid & 63, ks = tid >> 6;
  const float* uT_t = g_uT + (size_t)t * (INx * Bb);
  for (int i = tid; i < K1 * NC1; i += NTHR) {
    int kk = i / NC1, n = i % NC1, c = cid * NC1 + n;
    int row = (kk < Hh) ? (INx + kk) : (kk - Hh);
    float w;
    if (c < 2 * Hh) w = kernel_fz[row * (2 * Hh) + c];
    else { int o = c - 2 * Hh; w = (kk < Hh) ? W_out[o * Hh + kk] : 0.0f; }
    s_w1[i] = w;
  }
  if (tid < NC1) { int c = cid * NC1 + tid; s_b1[tid] = (c < 2 * Hh) ? bias_fz[c] : b_out[c - 2 * Hh]; }
  __syncthreads();
  float acc[NC1];
  #pragma unroll
  for (int n = 0; n < NC1; n++) acc[n] = 0.0f;
  {
    const float* xp = g_xT + (ks * 64) * Bb + m;
    const float* wp = s_w1 + (ks * 64) * NC1;
    #pragma unroll 8
    for (int k = 0; k < 64; k++) {
      float xv = xp[k * Bb];
      const float4* w4 = (const float4*)(wp + k * NC1);
      float4 wa = w4[0], wb = w4[1];
      acc[0] = fmaf(xv, wa.x, acc[0]); acc[1] = fmaf(xv, wa.y, acc[1]);
      acc[2] = fmaf(xv, wa.z, acc[2]); acc[3] = fmaf(xv, wa.w, acc[3]);
      acc[4] = fmaf(xv, wb.x, acc[4]); acc[5] = fmaf(xv, wb.y, acc[5]);
      acc[6] = fmaf(xv, wb.z, acc[6]); acc[7] = fmaf(xv, wb.w, acc[7]);
    }
  }
  {
    const float* up = uT_t + (ks * 8) * Bb + m;
    const float* wp = s_w1 + (Hh + ks * 8) * NC1;
    #pragma unroll
    for (int k = 0; k < 8; k++) {
      float uv = up[k * Bb];
      const float4* w4 = (const float4*)(wp + k * NC1);
      float4 wa = w4[0], wb = w4[1];
      acc[0] = fmaf(uv, wa.x, acc[0]); acc[1] = fmaf(uv, wa.y, acc[1]);
      acc[2] = fmaf(uv, wa.z, acc[2]); acc[3] = fmaf(uv, wa.w, acc[3]);
      acc[4] = fmaf(uv, wb.x, acc[4]); acc[5] = fmaf(uv, wb.y, acc[5]);
      acc[6] = fmaf(uv, wb.z, acc[6]); acc[7] = fmaf(uv, wb.w, acc[7]);
    }
  }
  #pragma unroll
  for (int n = 0; n < NC1; n++) s_red[tid * NC1 + n] = acc[n];
  __syncthreads();
  {
    int mm = tid & 63, n = tid >> 6;
    float s = s_b1[n];
    #pragma unroll
    for (int q = 0; q < 8; q++) s += s_red[(q * 64 + mm) * NC1 + n];
    int c = cid * NC1 + n;
    if (c < Hh) { float f = 1.0f / (1.0f + expf(-s)); g_xfT[c * Bb + mm] = f * g_xT[c * Bb + mm]; }
    else if (c < 2 * Hh) { g_z[(c - Hh) * Bb + mm] = 1.0f / (1.0f + expf(-s)); }
    else { out[((size_t)mm * Tt + t) * OUTD + (c - 2 * Hh)] = s; }
  }
}

__global__ void __launch_bounds__(NTHR, 1) phase2_kernel(
    const float* __restrict__ kernel_r, const float* __restrict__ bias_r, int t)
{
  __shared__ __align__(16) float s_w2[K1 * NC2];
  __shared__ float s_red[NTHR * NC2];
  __shared__ float s_b2[NC2];
  const int tid = threadIdx.x, cid = blockIdx.x;
  const int m = tid & 63, ks = tid >> 6;
  const float* uT_t = g_uT + (size_t)t * (INx * Bb);
  for (int i = tid; i < K1 * NC2; i += NTHR) {
    int kk = i / NC2, n = i % NC2, j = cid * NC2 + n;
    int row = (kk < Hh) ? (INx + kk) : (kk - Hh);
    s_w2[i] = kernel_r[row * Hh + j];
  }
  if (tid < NC2) s_b2[tid] = bias_r[cid * NC2 + tid];
  __syncthreads();
  float acc[NC2];
  #pragma unroll
  for (int n = 0; n < NC2; n++) acc[n] = 0.0f;
  {
    const float* xp = g_xfT + (ks * 64) * Bb + m;
    const float* wp = s_w2 + (ks * 64) * NC2;
    #pragma unroll 8
    for (int k = 0; k < 64; k++) {
      float xv = xp[k * Bb];
      float4 wa = *(const float4*)(wp + k * NC2);
      acc[0] = fmaf(xv, wa.x, acc[0]); acc[1] = fmaf(xv, wa.y, acc[1]);
      acc[2] = fmaf(xv, wa.z, acc[2]); acc[3] = fmaf(xv, wa.w, acc[3]);
    }
  }
  {
    const float* up = uT_t + (ks * 8) * Bb + m;
    const float* wp = s_w2 + (Hh + ks * 8) * NC2;
    #pragma unroll
    for (int k = 0; k < 8; k++) {
      float uv = up[k * Bb];
      float4 wa = *(const float4*)(wp + k * NC2);
      acc[0] = fmaf(uv, wa.x, acc[0]); acc[1] = fmaf(uv, wa.y, acc[1]);
      acc[2] = fmaf(uv, wa.z, acc[2]); acc[3] = fmaf(uv, wa.w, acc[3]);
    }
  }
  #pragma unroll
  for (int n = 0; n < NC2; n++) s_red[tid * NC2 + n] = acc[n];
  __syncthreads();
  if (tid < 256) {
    int mm = tid & 63, n = tid >> 6;
    float s = s_b2[n];
    #pragma unroll
    for (int q = 0; q < 8; q++) s += s_red[(q * 64 + mm) * NC2 + n];
    int c = cid * NC2 + n;
    float r = tanhf(s);
    float z = g_z[c * Bb + mm];
    float xo = g_xT[c * Bb + mm];
    g_xT[c * Bb + mm] = (1.0f - z) * xo + z * r;
  }
}

// ---- init kernels ----
__global__ void init_state_kernel(const float* __restrict__ x0) {
  int idx = blockIdx.x * blockDim.x + threadIdx.x;
  if (idx == 0) g_bar = 0u;
  if (idx < Hh * Bb) {
    int k = idx >> 6, mm = idx & 63;
    g_xT[idx] = x0[mm * Hh + k];      // x0 is (64, 1, 512)
  }
}

__global__ void transpose_u_kernel(const float* __restrict__ u) {
  __shared__ float tile[Bb * 65];     // [m][i], padded
  int t = blockIdx.x;
  for (int idx = threadIdx.x; idx < INx * Bb; idx += blockDim.x) {
    int mm = idx >> 6, i = idx & 63;
    tile[mm * 65 + i] = u[((size_t)mm * Tt + t) * INx + i];
  }
  __syncthreads();
  for (int idx = threadIdx.x; idx < INx * Bb; idx += blockDim.x) {
    g_uT[(size_t)t * (INx * Bb) + idx] = tile[(idx & 63) * 65 + (idx >> 6)];
  }
}

extern "C" void kernel_launch(void* const* d_in, const int* in_sizes, int n_in,
                              void* d_out, int out_size) {
  // Resolve inputs by UNIQUE element counts (immune to metadata ordering).
  const float *u = 0, *x0 = 0, *kernel_fz = 0, *bias_fz = 0,
              *kernel_r = 0, *bias_r = 0, *W_out = 0, *b_out = 0;
  for (int i = 0; i < n_in; i++) {
    const float* p = (const float*)d_in[i];
    switch (in_sizes[i]) {
      case 8388608: u         = p; break;  // 64*2048*64
      case 32768:   x0        = p; break;  // 64*1*512
      case 589824:  kernel_fz = p; break;  // 576*1024
      case 1024:    bias_fz   = p; break;
      case 294912:  kernel_r  = p; break;  // 576*512
      case 512:     bias_r    = p; break;
      case 16384:   W_out     = p; break;  // 32*512
      case 32:      b_out     = p; break;
      default: break;
    }
  }
  if (!u || !x0 || !kernel_fz || !bias_fz || !kernel_r || !bias_r || !W_out || !b_out) {
    u         = (const float*)d_in[0];
    x0        = (const float*)d_in[1];
    kernel_fz = (const float*)d_in[2];
    bias_fz   = (const float*)d_in[3];
    kernel_r  = (const float*)d_in[4];
    bias_r    = (const float*)d_in[5];
    W_out     = (const float*)d_in[6];
    b_out     = (const float*)d_in[7];
  }
  float* out = (float*)d_out;

  init_state_kernel<<<(Hh * Bb + 255) / 256, 256>>>(x0);
  transpose_u_kernel<<<Tt, 256>>>(u);

  // Persistent cooperative kernel: driver validates co-residency for the
  // grid-wide barrier. Single graph node for the whole recurrence.
  void* args[] = { (void*)&kernel_fz, (void*)&bias_fz, (void*)&kernel_r,
                   (void*)&bias_r,    (void*)&W_out,   (void*)&b_out,
                   (void*)&out };
  cudaError_t e = cudaLaunchCooperativeKernel(
      (const void*)gru_main, dim3(NCTA1), dim3(NTHR), args, 0, (cudaStream_t)0);
  if (e != cudaSuccess) {
    (void)cudaGetLastError();
    // Diagnostic fallback: round-5 per-step launches (correct, but trips the
    // graph-teardown rule -> tells us cooperative launch was the problem).
    for (int t = 0; t < Tt; t++) {
      phase1_kernel<<<NCTA1, NTHR>>>(kernel_fz, bias_fz, W_out, b_out, out, t);
      phase2_kernel<<<NCTA2, NTHR>>>(kernel_r, bias_r, t);
    }
  }
}

// round 7
// speedup vs baseline: 1.0695x; 1.0695x over previous
#include <cuda_runtime.h>
#include <math.h>
#include <stdint.h>

// Problem dims
#define Bb   64
#define Tt   2048
#define INx  64
#define Hh   512
#define OUTD 32
#define K1   576      // INx + Hh
#define NCTA1 132     // 132*8 = 1056 = 1024 fz cols + 32 y cols
#define NC1  8        // phase-1 cols per CTA
#define NCTA2 128     // 128*4 = 512 r cols
#define NC2  4        // phase-2 cols per CTA
#define NTHR 512      // m = tid & 63, ks = tid >> 6 (8 K-slices)

typedef unsigned long long ull;

// ---- persistent device scratch (no allocation allowed) ----
__device__ float g_xT [Hh * Bb];               // state, transposed [k][m]
__device__ float g_xfT[Hh * Bb];               // f*x, transposed  [k][m]
__device__ float g_z  [Hh * Bb];               // z gate           [j][m]
__device__ float g_uT [(size_t)Tt * INx * Bb]; // u transposed: [t][i][m]  (32 MB)
__device__ unsigned g_bar;

// Hardened grid barrier (round-6-proven fencing kept verbatim):
//  - EVERY thread executes __threadfence() on both release and acquire sides.
//  - Arrival: one atomicAdd per CTA. Spin: ld.acquire.gpu loads (no RMW
//    serialization at the LTS, unlike atomicAdd polling).
__device__ __forceinline__ void grid_barrier(unsigned target) {
  __threadfence();                    // release: per-SM drain/flush, all threads
  __syncthreads();
  if (threadIdx.x == 0) {
    atomicAdd(&g_bar, 1u);
    unsigned v;
    do {
      asm volatile("ld.acquire.gpu.global.u32 %0, [%1];"
                   : "=r"(v) : "l"(&g_bar) : "memory");
    } while (v < target);
  }
  __syncthreads();
  __threadfence();                    // acquire: flush L1 before post-barrier loads
}

__device__ __forceinline__ ull bcast2(float v) {
  ull r;
  asm("mov.b64 %0, {%1, %1};" : "=l"(r) : "r"(__float_as_uint(v)));
  return r;
}

__global__ void __launch_bounds__(NTHR, 1) gru_main(
    const float* __restrict__ kernel_fz, const float* __restrict__ bias_fz,
    const float* __restrict__ kernel_r,  const float* __restrict__ bias_r,
    const float* __restrict__ W_out,     const float* __restrict__ b_out,
    float* __restrict__ out)
{
  __shared__ __align__(16) float s_w1[K1 * NC1];  // [kk][n], kk 0..511=x rows, 512..575=u rows
  __shared__ __align__(16) float s_w2[K1 * NC2];
  __shared__ __align__(16) float s_red[NTHR * NC1];
  __shared__ float s_b1[NC1];
  __shared__ float s_b2[NC2];

  const int tid = threadIdx.x;
  const int cid = blockIdx.x;
  const int m   = tid & 63;   // batch row
  const int ks  = tid >> 6;   // K-slice 0..7

  // ---- stationary weight slices into SMEM (once) ----
  for (int i = tid; i < K1 * NC1; i += NTHR) {
    int kk = i / NC1, n = i % NC1;
    int c  = cid * NC1 + n;
    int row = (kk < Hh) ? (INx + kk) : (kk - Hh);   // concat order: [u | x]
    float w;
    if (c < 2 * Hh) w = kernel_fz[row * (2 * Hh) + c];
    else { int o = c - 2 * Hh; w = (kk < Hh) ? W_out[o * Hh + kk] : 0.0f; }
    s_w1[i] = w;
  }
  if (cid < NCTA2) {
    for (int i = tid; i < K1 * NC2; i += NTHR) {
      int kk = i / NC2, n = i % NC2;
      int j  = cid * NC2 + n;
      int row = (kk < Hh) ? (INx + kk) : (kk - Hh);
      s_w2[i] = kernel_r[row * Hh + j];
    }
  }
  if (tid < NC1) {
    int c = cid * NC1 + tid;
    s_b1[tid] = (c < 2 * Hh) ? bias_fz[c] : b_out[c - 2 * Hh];
  }
  if (cid < NCTA2 && tid < NC2) s_b2[tid] = bias_r[cid * NC2 + tid];
  __syncthreads();

  unsigned target = 0;
  for (int t = 0; t < Tt; t++) {
    const float* uT_t = g_uT + (size_t)t * (INx * Bb);

    // ================= phase 1: fz logits + y readout =================
    {
      ull acc[NC1 / 2] = {0ull, 0ull, 0ull, 0ull};

      { // x segment: rows [ks*64, ks*64+64)
        const float* xp = g_xT + (ks * 64) * Bb + m;
        const ull*   wp = (const ull*)(s_w1 + (ks * 64) * NC1);
        #pragma unroll 8
        for (int k = 0; k < 64; k++) {
          ull xx = bcast2(xp[k * Bb]);
          const ull* wr = wp + k * (NC1 / 2);
          asm("fma.rn.f32x2 %0, %1, %2, %0;" : "+l"(acc[0]) : "l"(xx), "l"(wr[0]));
          asm("fma.rn.f32x2 %0, %1, %2, %0;" : "+l"(acc[1]) : "l"(xx), "l"(wr[1]));
          asm("fma.rn.f32x2 %0, %1, %2, %0;" : "+l"(acc[2]) : "l"(xx), "l"(wr[2]));
          asm("fma.rn.f32x2 %0, %1, %2, %0;" : "+l"(acc[3]) : "l"(xx), "l"(wr[3]));
        }
      }
      { // u segment: rows [512 + ks*8, 512 + ks*8 + 8)
        const float* up = uT_t + (ks * 8) * Bb + m;
        const ull*   wp = (const ull*)(s_w1 + (Hh + ks * 8) * NC1);
        #pragma unroll
        for (int k = 0; k < 8; k++) {
          ull xx = bcast2(up[k * Bb]);
          const ull* wr = wp + k * (NC1 / 2);
          asm("fma.rn.f32x2 %0, %1, %2, %0;" : "+l"(acc[0]) : "l"(xx), "l"(wr[0]));
          asm("fma.rn.f32x2 %0, %1, %2, %0;" : "+l"(acc[1]) : "l"(xx), "l"(wr[1]));
          asm("fma.rn.f32x2 %0, %1, %2, %0;" : "+l"(acc[2]) : "l"(xx), "l"(wr[2]));
          asm("fma.rn.f32x2 %0, %1, %2, %0;" : "+l"(acc[3]) : "l"(xx), "l"(wr[3]));
        }
      }
      // pair lane0 = low word = even column: same layout as float writes
      {
        ull* rr = (ull*)&s_red[tid * NC1];
        rr[0] = acc[0]; rr[1] = acc[1]; rr[2] = acc[2]; rr[3] = acc[3];
      }
      __syncthreads();

      { // epilogue: 512 threads -> 64 batch x 8 cols
        int mm = tid & 63, n = tid >> 6;
        float s = s_b1[n];
        #pragma unroll
        for (int q = 0; q < 8; q++) s += s_red[(q * 64 + mm) * NC1 + n];
        int c = cid * NC1 + n;
        if (c < Hh) {                                  // f gate -> f*x
          float f  = 1.0f / (1.0f + expf(-s));
          g_xfT[c * Bb + mm] = f * g_xT[c * Bb + mm];
        } else if (c < 2 * Hh) {                       // z gate
          g_z[(c - Hh) * Bb + mm] = 1.0f / (1.0f + expf(-s));
        } else {                                       // y readout (pre-update x)
          out[((size_t)mm * Tt + t) * OUTD + (c - 2 * Hh)] = s;
        }
      }
    }
    target += NCTA1;
    grid_barrier(target);

    // ================= phase 2: r + state update =================
    if (cid < NCTA2) {
      ull acc[NC2 / 2] = {0ull, 0ull};

      {
        const float* xp = g_xfT + (ks * 64) * Bb + m;
        const ull*   wp = (const ull*)(s_w2 + (ks * 64) * NC2);
        #pragma unroll 8
        for (int k = 0; k < 64; k++) {
          ull xx = bcast2(xp[k * Bb]);
          const ull* wr = wp + k * (NC2 / 2);
          asm("fma.rn.f32x2 %0, %1, %2, %0;" : "+l"(acc[0]) : "l"(xx), "l"(wr[0]));
          asm("fma.rn.f32x2 %0, %1, %2, %0;" : "+l"(acc[1]) : "l"(xx), "l"(wr[1]));
        }
      }
      {
        const float* up = uT_t + (ks * 8) * Bb + m;
        const ull*   wp = (const ull*)(s_w2 + (Hh + ks * 8) * NC2);
        #pragma unroll
        for (int k = 0; k < 8; k++) {
          ull xx = bcast2(up[k * Bb]);
          const ull* wr = wp + k * (NC2 / 2);
          asm("fma.rn.f32x2 %0, %1, %2, %0;" : "+l"(acc[0]) : "l"(xx), "l"(wr[0]));
          asm("fma.rn.f32x2 %0, %1, %2, %0;" : "+l"(acc[1]) : "l"(xx), "l"(wr[1]));
        }
      }
      {
        ull* rr = (ull*)&s_red[tid * NC2];
        rr[0] = acc[0]; rr[1] = acc[1];
      }
      __syncthreads();

      if (tid < 256) {                  // 64 batch x 4 cols
        int mm = tid & 63, n = tid >> 6;
        float s = s_b2[n];
        #pragma unroll
        for (int q = 0; q < 8; q++) s += s_red[(q * 64 + mm) * NC2 + n];
        int c = cid * NC2 + n;
        float r  = tanhf(s);
        float z  = g_z[c * Bb + mm];
        float xo = g_xT[c * Bb + mm];
        g_xT[c * Bb + mm] = (1.0f - z) * xo + z * r;
      }
    }
    target += NCTA1;
    grid_barrier(target);
  }
}

// ---- init kernels ----
__global__ void init_state_kernel(const float* __restrict__ x0) {
  int idx = blockIdx.x * blockDim.x + threadIdx.x;
  if (idx == 0) g_bar = 0u;
  if (idx < Hh * Bb) {
    int k = idx >> 6, mm = idx & 63;
    g_xT[idx] = x0[mm * Hh + k];      // x0 is (64, 1, 512)
  }
}

__global__ void transpose_u_kernel(const float* __restrict__ u) {
  __shared__ float tile[Bb * 65];     // [m][i], padded
  int t = blockIdx.x;
  for (int idx = threadIdx.x; idx < INx * Bb; idx += blockDim.x) {
    int mm = idx >> 6, i = idx & 63;
    tile[mm * 65 + i] = u[((size_t)mm * Tt + t) * INx + i];
  }
  __syncthreads();
  for (int idx = threadIdx.x; idx < INx * Bb; idx += blockDim.x) {
    g_uT[(size_t)t * (INx * Bb) + idx] = tile[(idx & 63) * 65 + (idx >> 6)];
  }
}

extern "C" void kernel_launch(void* const* d_in, const int* in_sizes, int n_in,
                              void* d_out, int out_size) {
  // Resolve inputs by UNIQUE element counts (immune to metadata ordering).
  const float *u = 0, *x0 = 0, *kernel_fz = 0, *bias_fz = 0,
              *kernel_r = 0, *bias_r = 0, *W_out = 0, *b_out = 0;
  for (int i = 0; i < n_in; i++) {
    const float* p = (const float*)d_in[i];
    switch (in_sizes[i]) {
      case 8388608: u         = p; break;  // 64*2048*64
      case 32768:   x0        = p; break;  // 64*1*512
      case 589824:  kernel_fz = p; break;  // 576*1024
      case 1024:    bias_fz   = p; break;
      case 294912:  kernel_r  = p; break;  // 576*512
      case 512:     bias_r    = p; break;
      case 16384:   W_out     = p; break;  // 32*512
      case 32:      b_out     = p; break;
      default: break;
    }
  }
  if (!u || !x0 || !kernel_fz || !bias_fz || !kernel_r || !bias_r || !W_out || !b_out) {
    u         = (const float*)d_in[0];
    x0        = (const float*)d_in[1];
    kernel_fz = (const float*)d_in[2];
    bias_fz   = (const float*)d_in[3];
    kernel_r  = (const float*)d_in[4];
    bias_r    = (const float*)d_in[5];
    W_out     = (const float*)d_in[6];
    b_out     = (const float*)d_in[7];
  }
  float* out = (float*)d_out;

  init_state_kernel<<<(Hh * Bb + 255) / 256, 256>>>(x0);
  transpose_u_kernel<<<Tt, 256>>>(u);

  void* args[] = { (void*)&kernel_fz, (void*)&bias_fz, (void*)&kernel_r,
                   (void*)&bias_r,    (void*)&W_out,   (void*)&b_out,
                   (void*)&out };
  cudaLaunchCooperativeKernel((const void*)gru_main, dim3(NCTA1), dim3(NTHR),
                              args, 0, (cudaStream_t)0);
}

// round 8
// speedup vs baseline: 1.2339x; 1.1538x over previous
#include <cuda_runtime.h>
#include <math.h>
#include <stdint.h>

// Problem dims
#define Bb   64
#define Tt   2048
#define INx  64
#define Hh   512
#define OUTD 32
#define K1   576      // INx + Hh
#define NCTA1 132     // 132*8 = 1056 = 1024 fz cols + 32 y cols
#define NC1  8        // phase-1 cols per CTA
#define NCTA2 128     // 128*4 = 512 r cols
#define NC2  4        // phase-2 cols per CTA
#define NTHR 512      // m = tid & 63, ks = tid >> 6 (8 K-slices)

typedef unsigned long long ull;

// ---- persistent device scratch (no allocation allowed) ----
__device__ float g_xT [Hh * Bb];               // state, transposed [k][m]
__device__ float g_xfT[Hh * Bb];               // f*x, transposed  [k][m]
__device__ float g_z  [Hh * Bb];               // z gate           [j][m]
__device__ float g_uT [(size_t)Tt * INx * Bb]; // u transposed: [t][i][m]  (32 MB)
__device__ unsigned g_bar;

__device__ __forceinline__ ull bcast2(float v) {
  ull r;
  asm("mov.b64 %0, {%1, %1};" : "=l"(r) : "r"(__float_as_uint(v)));
  return r;
}
__device__ __forceinline__ unsigned bar_poll() {
  unsigned v;
  asm volatile("ld.acquire.gpu.global.u32 %0, [%1];" : "=r"(v) : "l"(&g_bar) : "memory");
  return v;
}

__global__ void __launch_bounds__(NTHR, 1) gru_main(
    const float* __restrict__ kernel_fz, const float* __restrict__ bias_fz,
    const float* __restrict__ kernel_r,  const float* __restrict__ bias_r,
    const float* __restrict__ W_out,     const float* __restrict__ b_out,
    float* __restrict__ out)
{
  __shared__ __align__(16) float s_w1[K1 * NC1];  // [kk][n], kk 0..511=x rows, 512..575=u rows
  __shared__ __align__(16) float s_w2[K1 * NC2];
  __shared__ __align__(16) float s_red[NTHR * NC1];
  __shared__ float s_b1[NC1];
  __shared__ float s_b2[NC2];

  const int tid = threadIdx.x;
  const int cid = blockIdx.x;
  const int m   = tid & 63;   // batch row
  const int ks  = tid >> 6;   // K-slice 0..7

  // ---- stationary weight slices into SMEM (once) ----
  for (int i = tid; i < K1 * NC1; i += NTHR) {
    int kk = i / NC1, n = i % NC1;
    int c  = cid * NC1 + n;
    int row = (kk < Hh) ? (INx + kk) : (kk - Hh);   // concat order: [u | x]
    float w;
    if (c < 2 * Hh) w = kernel_fz[row * (2 * Hh) + c];
    else { int o = c - 2 * Hh; w = (kk < Hh) ? W_out[o * Hh + kk] : 0.0f; }
    s_w1[i] = w;
  }
  if (cid < NCTA2) {
    for (int i = tid; i < K1 * NC2; i += NTHR) {
      int kk = i / NC2, n = i % NC2;
      int j  = cid * NC2 + n;
      int row = (kk < Hh) ? (INx + kk) : (kk - Hh);
      s_w2[i] = kernel_r[row * Hh + j];
    }
  }
  if (tid < NC1) {
    int c = cid * NC1 + tid;
    s_b1[tid] = (c < 2 * Hh) ? bias_fz[c] : b_out[c - 2 * Hh];
  }
  if (cid < NCTA2 && tid < NC2) s_b2[tid] = bias_r[cid * NC2 + tid];
  __syncthreads();

  // ---- prologue: phase-1 u-segment for t = 0 ----
  ull acc1u[NC1 / 2];
  {
    const float* up = g_uT + (ks * 8) * Bb + m;
    const ull*   wp = (const ull*)(s_w1 + (Hh + ks * 8) * NC1);
    acc1u[0] = acc1u[1] = acc1u[2] = acc1u[3] = 0ull;
    #pragma unroll
    for (int k = 0; k < 8; k++) {
      ull xx = bcast2(up[k * Bb]);
      const ulonglong2* wv = (const ulonglong2*)(wp + k * (NC1 / 2));
      ulonglong2 wA = wv[0], wB = wv[1];
      asm("fma.rn.f32x2 %0, %1, %2, %0;" : "+l"(acc1u[0]) : "l"(xx), "l"(wA.x));
      asm("fma.rn.f32x2 %0, %1, %2, %0;" : "+l"(acc1u[1]) : "l"(xx), "l"(wA.y));
      asm("fma.rn.f32x2 %0, %1, %2, %0;" : "+l"(acc1u[2]) : "l"(xx), "l"(wB.x));
      asm("fma.rn.f32x2 %0, %1, %2, %0;" : "+l"(acc1u[3]) : "l"(xx), "l"(wB.y));
    }
  }

  unsigned target = 0;
  for (int t = 0; t < Tt; t++) {
    const float* uT_t = g_uT + (size_t)t * (INx * Bb);

    // ================= phase 1: fz logits + y readout =================
    {
      ull acc[NC1 / 2] = {acc1u[0], acc1u[1], acc1u[2], acc1u[3]};

      { // x segment: rows [ks*64, ks*64+64)
        const float* xp = g_xT + (ks * 64) * Bb + m;
        const ull*   wp = (const ull*)(s_w1 + (ks * 64) * NC1);
        #pragma unroll 8
        for (int k = 0; k < 64; k++) {
          ull xx = bcast2(__ldcg(xp + k * Bb));
          const ulonglong2* wv = (const ulonglong2*)(wp + k * (NC1 / 2));
          ulonglong2 wA = wv[0], wB = wv[1];
          asm("fma.rn.f32x2 %0, %1, %2, %0;" : "+l"(acc[0]) : "l"(xx), "l"(wA.x));
          asm("fma.rn.f32x2 %0, %1, %2, %0;" : "+l"(acc[1]) : "l"(xx), "l"(wA.y));
          asm("fma.rn.f32x2 %0, %1, %2, %0;" : "+l"(acc[2]) : "l"(xx), "l"(wB.x));
          asm("fma.rn.f32x2 %0, %1, %2, %0;" : "+l"(acc[3]) : "l"(xx), "l"(wB.y));
        }
      }
      {
        ull* rr = (ull*)&s_red[tid * NC1];
        rr[0] = acc[0]; rr[1] = acc[1]; rr[2] = acc[2]; rr[3] = acc[3];
      }
      __syncthreads();

      { // epilogue: 512 threads -> 64 batch x 8 cols
        int mm = tid & 63, n = tid >> 6;
        float s = s_b1[n];
        #pragma unroll
        for (int q = 0; q < 8; q++) s += s_red[(q * 64 + mm) * NC1 + n];
        int c = cid * NC1 + n;
        if (c < Hh) {                                  // f gate -> f*x
          float f  = 1.0f / (1.0f + expf(-s));
          g_xfT[c * Bb + mm] = f * __ldcg(&g_xT[c * Bb + mm]);
        } else if (c < 2 * Hh) {                       // z gate
          g_z[(c - Hh) * Bb + mm] = 1.0f / (1.0f + expf(-s));
        } else {                                       // y readout (pre-update x)
          out[((size_t)mm * Tt + t) * OUTD + (c - 2 * Hh)] = s;
        }
      }
    }
    // ---- barrier 1: release (writers only) + arrive, overlap, wait ----
    if (cid < NCTA2) __threadfence();        // CTAs 128-131 wrote only `out`
    __syncthreads();
    if (tid == 0) atomicAdd(&g_bar, 1u);
    target += NCTA1;

    // overlap: phase-2 u-segment (depends only on g_uT)
    ull acc2[NC2 / 2] = {0ull, 0ull};
    if (cid < NCTA2) {
      const float* up = uT_t + (ks * 8) * Bb + m;
      const ull*   wp = (const ull*)(s_w2 + (Hh + ks * 8) * NC2);
      #pragma unroll
      for (int k = 0; k < 8; k++) {
        ull xx = bcast2(up[k * Bb]);
        ulonglong2 wA = *(const ulonglong2*)(wp + k * (NC2 / 2));
        asm("fma.rn.f32x2 %0, %1, %2, %0;" : "+l"(acc2[0]) : "l"(xx), "l"(wA.x));
        asm("fma.rn.f32x2 %0, %1, %2, %0;" : "+l"(acc2[1]) : "l"(xx), "l"(wA.y));
      }
    }
    if (tid == 0) { while (bar_poll() < target) { } }
    __syncthreads();

    // ================= phase 2: r + state update =================
    if (cid < NCTA2) {
      {
        const float* xp = g_xfT + (ks * 64) * Bb + m;
        const ull*   wp = (const ull*)(s_w2 + (ks * 64) * NC2);
        #pragma unroll 8
        for (int k = 0; k < 64; k++) {
          ull xx = bcast2(__ldcg(xp + k * Bb));
          ulonglong2 wA = *(const ulonglong2*)(wp + k * (NC2 / 2));
          asm("fma.rn.f32x2 %0, %1, %2, %0;" : "+l"(acc2[0]) : "l"(xx), "l"(wA.x));
          asm("fma.rn.f32x2 %0, %1, %2, %0;" : "+l"(acc2[1]) : "l"(xx), "l"(wA.y));
        }
      }
      {
        ull* rr = (ull*)&s_red[tid * NC2];
        rr[0] = acc2[0]; rr[1] = acc2[1];
      }
      __syncthreads();

      if (tid < 256) {                  // 64 batch x 4 cols
        int mm = tid & 63, n = tid >> 6;
        float s = s_b2[n];
        #pragma unroll
        for (int q = 0; q < 8; q++) s += s_red[(q * 64 + mm) * NC2 + n];
        int c = cid * NC2 + n;
        float r  = tanhf(s);
        float z  = __ldcg(&g_z[c * Bb + mm]);
        float xo = __ldcg(&g_xT[c * Bb + mm]);
        g_xT[c * Bb + mm] = (1.0f - z) * xo + z * r;
      }
    }
    // ---- barrier 2: release (writers only) + arrive, overlap, wait ----
    if (cid < NCTA2 && tid < 256) __threadfence();
    __syncthreads();
    if (tid == 0) atomicAdd(&g_bar, 1u);
    target += NCTA1;

    // overlap: phase-1 u-segment for t+1 (clamped; last iter redundant)
    {
      int tn = (t + 1 < Tt) ? (t + 1) : (Tt - 1);
      const float* up = g_uT + (size_t)tn * (INx * Bb) + (ks * 8) * Bb + m;
      const ull*   wp = (const ull*)(s_w1 + (Hh + ks * 8) * NC1);
      acc1u[0] = acc1u[1] = acc1u[2] = acc1u[3] = 0ull;
      #pragma unroll
      for (int k = 0; k < 8; k++) {
        ull xx = bcast2(up[k * Bb]);
        const ulonglong2* wv = (const ulonglong2*)(wp + k * (NC1 / 2));
        ulonglong2 wA = wv[0], wB = wv[1];
        asm("fma.rn.f32x2 %0, %1, %2, %0;" : "+l"(acc1u[0]) : "l"(xx), "l"(wA.x));
        asm("fma.rn.f32x2 %0, %1, %2, %0;" : "+l"(acc1u[1]) : "l"(xx), "l"(wA.y));
        asm("fma.rn.f32x2 %0, %1, %2, %0;" : "+l"(acc1u[2]) : "l"(xx), "l"(wB.x));
        asm("fma.rn.f32x2 %0, %1, %2, %0;" : "+l"(acc1u[3]) : "l"(xx), "l"(wB.y));
      }
    }
    if (tid == 0) { while (bar_poll() < target) { } }
    __syncthreads();
  }
}

// ---- init kernels ----
__global__ void init_state_kernel(const float* __restrict__ x0) {
  int idx = blockIdx.x * blockDim.x + threadIdx.x;
  if (idx == 0) g_bar = 0u;
  if (idx < Hh * Bb) {
    int k = idx >> 6, mm = idx & 63;
    g_xT[idx] = x0[mm * Hh + k];      // x0 is (64, 1, 512)
  }
}

__global__ void transpose_u_kernel(const float* __restrict__ u) {
  __shared__ float tile[Bb * 65];     // [m][i], padded
  int t = blockIdx.x;
  for (int idx = threadIdx.x; idx < INx * Bb; idx += blockDim.x) {
    int mm = idx >> 6, i = idx & 63;
    tile[mm * 65 + i] = u[((size_t)mm * Tt + t) * INx + i];
  }
  __syncthreads();
  for (int idx = threadIdx.x; idx < INx * Bb; idx += blockDim.x) {
    g_uT[(size_t)t * (INx * Bb) + idx] = tile[(idx & 63) * 65 + (idx >> 6)];
  }
}

extern "C" void kernel_launch(void* const* d_in, const int* in_sizes, int n_in,
                              void* d_out, int out_size) {
  // Resolve inputs by UNIQUE element counts (immune to metadata ordering).
  const float *u = 0, *x0 = 0, *kernel_fz = 0, *bias_fz = 0,
              *kernel_r = 0, *bias_r = 0, *W_out = 0, *b_out = 0;
  for (int i = 0; i < n_in; i++) {
    const float* p = (const float*)d_in[i];
    switch (in_sizes[i]) {
      case 8388608: u         = p; break;  // 64*2048*64
      case 32768:   x0        = p; break;  // 64*1*512
      case 589824:  kernel_fz = p; break;  // 576*1024
      case 1024:    bias_fz   = p; break;
      case 294912:  kernel_r  = p; break;  // 576*512
      case 512:     bias_r    = p; break;
      case 16384:   W_out     = p; break;  // 32*512
      case 32:      b_out     = p; break;
      default: break;
    }
  }
  if (!u || !x0 || !kernel_fz || !bias_fz || !kernel_r || !bias_r || !W_out || !b_out) {
    u         = (const float*)d_in[0];
    x0        = (const float*)d_in[1];
    kernel_fz = (const float*)d_in[2];
    bias_fz   = (const float*)d_in[3];
    kernel_r  = (const float*)d_in[4];
    bias_r    = (const float*)d_in[5];
    W_out     = (const float*)d_in[6];
    b_out     = (const float*)d_in[7];
  }
  float* out = (float*)d_out;

  init_state_kernel<<<(Hh * Bb + 255) / 256, 256>>>(x0);
  transpose_u_kernel<<<Tt, 256>>>(u);

  void* args[] = { (void*)&kernel_fz, (void*)&bias_fz, (void*)&kernel_r,
                   (void*)&bias_r,    (void*)&W_out,   (void*)&b_out,
                   (void*)&out };
  cudaLaunchCooperativeKernel((const void*)gru_main, dim3(NCTA1), dim3(NTHR),
                              args, 0, (cudaStream_t)0);
}

// round 9
// speedup vs baseline: 1.3326x; 1.0800x over previous
#include <cuda_runtime.h>
#include <math.h>
#include <stdint.h>

// Problem dims
#define Bb   64
#define Tt   2048
#define INx  64
#define Hh   512
#define OUTD 32
#define K1   576      // INx + Hh
#define NCTA1 132     // 132*8 = 1056 = 1024 fz cols + 32 y cols
#define NC1  8        // phase-1 cols per CTA
#define NCTA2 128     // 128*4 = 512 r cols
#define NC2  4        // phase-2 cols per CTA
#define NTHR 512
#define NSL  16       // K-slices = warps; each warp owns 32 x-rows + 4 u-rows; lane = m-pair

typedef unsigned long long ull;

// ---- persistent device scratch (no allocation allowed) ----
__device__ float g_xT [Hh * Bb];               // state, transposed [k][m]
__device__ float g_xfT[Hh * Bb];               // f*x, transposed  [k][m]
__device__ float g_z  [Hh * Bb];               // z gate           [j][m]
__device__ float g_uT [(size_t)Tt * INx * Bb]; // u transposed: [t][i][m]  (32 MB)
__device__ unsigned g_bar = 0u;                // reset by trailing zero_bar_kernel

// SMEM layout (floats) in dynamic shared memory
#define OFF_W1  0                    // 576*8  = 4608
#define OFF_W2  4608                 // 576*4  = 2304
#define OFF_RED 6912                 // 16*64*8 = 8192 (also reused as transpose tile)
#define OFF_B1  15104                // 8
#define OFF_B2  15112                // 8 (4 used)
#define SMEM_FLOATS 15120
#define SMEM_BYTES  (SMEM_FLOATS * 4)

__device__ __forceinline__ ull bcast2(float v) {
  ull r;
  asm("mov.b64 %0, {%1, %1};" : "=l"(r) : "r"(__float_as_uint(v)));
  return r;
}
__device__ __forceinline__ unsigned bar_poll() {
  unsigned v;
  asm volatile("ld.acquire.gpu.global.u32 %0, [%1];" : "=r"(v) : "l"(&g_bar) : "memory");
  return v;
}

__global__ void __launch_bounds__(NTHR, 1) gru_main(
    const float* __restrict__ u,
    const float* __restrict__ x0,
    const float* __restrict__ kernel_fz, const float* __restrict__ bias_fz,
    const float* __restrict__ kernel_r,  const float* __restrict__ bias_r,
    const float* __restrict__ W_out,     const float* __restrict__ b_out,
    float* __restrict__ out)
{
  extern __shared__ float smem[];
  float* s_w1  = smem + OFF_W1;   // [kk][n], kk 0..511 = x rows, 512..575 = u rows
  float* s_w2  = smem + OFF_W2;
  float* s_red = smem + OFF_RED;
  float* s_b1  = smem + OFF_B1;
  float* s_b2  = smem + OFF_B2;

  const int tid = threadIdx.x;
  const int cid = blockIdx.x;
  const int mg  = tid & 31;    // m-pair group: handles batch rows 2mg, 2mg+1
  const int ks  = tid >> 5;    // K-slice 0..15 (= warp id)
  const int m0  = 2 * mg;

  unsigned target = 0;

  // ---- stationary weight slices into SMEM ----
  for (int i = tid; i < K1 * NC1; i += NTHR) {
    int kk = i / NC1, n = i % NC1;
    int c  = cid * NC1 + n;
    int row = (kk < Hh) ? (INx + kk) : (kk - Hh);   // concat order: [u | x]
    float w;
    if (c < 2 * Hh) w = kernel_fz[row * (2 * Hh) + c];
    else { int o = c - 2 * Hh; w = (kk < Hh) ? W_out[o * Hh + kk] : 0.0f; }
    s_w1[i] = w;
  }
  if (cid < NCTA2) {
    for (int i = tid; i < K1 * NC2; i += NTHR) {
      int kk = i / NC2, n = i % NC2;
      int j  = cid * NC2 + n;
      int row = (kk < Hh) ? (INx + kk) : (kk - Hh);
      s_w2[i] = kernel_r[row * Hh + j];
    }
  }
  if (tid < NC1) {
    int c = cid * NC1 + tid;
    s_b1[tid] = (c < 2 * Hh) ? bias_fz[c] : b_out[c - 2 * Hh];
  }
  if (cid < NCTA2 && tid < NC2) s_b2[tid] = bias_r[cid * NC2 + tid];

  // ---- in-kernel init: x0 -> g_xT (grid-stride) ----
  for (int idx = cid * NTHR + tid; idx < Hh * Bb; idx += NCTA1 * NTHR) {
    int k = idx >> 6, mm = idx & 63;
    g_xT[idx] = x0[mm * Hh + k];          // x0 is (64, 1, 512)
  }

  // ---- in-kernel u transpose: u(B,T,IN) -> g_uT[t][i][m] ----
  {
    float* tile = s_red;                  // 64*65 = 4160 floats, fits in RED region
    __syncthreads();                      // weights done before tile reuse? tile overlaps nothing of w1/w2
    for (int t = cid; t < Tt; t += NCTA1) {
      for (int idx = tid; idx < INx * Bb; idx += NTHR) {
        int mm = idx >> 6, i = idx & 63;  // coalesced read over i
        tile[mm * 65 + i] = u[((size_t)mm * Tt + t) * INx + i];
      }
      __syncthreads();
      for (int idx = tid; idx < INx * Bb; idx += NTHR) {
        g_uT[(size_t)t * (INx * Bb) + idx] = tile[(idx & 63) * 65 + (idx >> 6)];
      }
      __syncthreads();
    }
  }

  // ---- grid barrier after init/transpose ----
  __threadfence();
  __syncthreads();
  if (tid == 0) atomicAdd(&g_bar, 1u);
  target += NCTA1;
  if (tid == 0) { while (bar_poll() < target) { } }
  __syncthreads();

  // ---- prologue: phase-1 u-segment for t = 0 ----
  ull acc1u[NC1];    // 2 m's x 8 cols = 16 floats = 8 ull: [m0 c01,c23,c45,c67, m1 ...]
  {
    #pragma unroll
    for (int p = 0; p < 8; p++) acc1u[p] = 0ull;
    const float2* up = (const float2*)(g_uT + (ks * 4) * Bb + m0);
    const ull*    wp = (const ull*)(s_w1 + (Hh + ks * 4) * NC1);
    #pragma unroll
    for (int k = 0; k < 4; k++) {
      float2 xv = up[k * (Bb / 2)];
      ull x0b = bcast2(xv.x), x1b = bcast2(xv.y);
      const ulonglong2* wv = (const ulonglong2*)(wp + k * (NC1 / 2));
      ulonglong2 wA = wv[0], wB = wv[1];
      asm("fma.rn.f32x2 %0, %1, %2, %0;" : "+l"(acc1u[0]) : "l"(x0b), "l"(wA.x));
      asm("fma.rn.f32x2 %0, %1, %2, %0;" : "+l"(acc1u[1]) : "l"(x0b), "l"(wA.y));
      asm("fma.rn.f32x2 %0, %1, %2, %0;" : "+l"(acc1u[2]) : "l"(x0b), "l"(wB.x));
      asm("fma.rn.f32x2 %0, %1, %2, %0;" : "+l"(acc1u[3]) : "l"(x0b), "l"(wB.y));
      asm("fma.rn.f32x2 %0, %1, %2, %0;" : "+l"(acc1u[4]) : "l"(x1b), "l"(wA.x));
      asm("fma.rn.f32x2 %0, %1, %2, %0;" : "+l"(acc1u[5]) : "l"(x1b), "l"(wA.y));
      asm("fma.rn.f32x2 %0, %1, %2, %0;" : "+l"(acc1u[6]) : "l"(x1b), "l"(wB.x));
      asm("fma.rn.f32x2 %0, %1, %2, %0;" : "+l"(acc1u[7]) : "l"(x1b), "l"(wB.y));
    }
  }

  for (int t = 0; t < Tt; t++) {
    const float* uT_t = g_uT + (size_t)t * (INx * Bb);

    // ================= phase 1: fz logits + y readout =================
    {
      ull acc[8];
      #pragma unroll
      for (int p = 0; p < 8; p++) acc[p] = acc1u[p];

      { // x segment: rows [ks*32, ks*32+32)
        const float2* xp = (const float2*)(g_xT + (ks * 32) * Bb + m0);
        const ull*    wp = (const ull*)(s_w1 + (ks * 32) * NC1);
        #pragma unroll 8
        for (int k = 0; k < 32; k++) {
          float2 xv = __ldcg(xp + k * (Bb / 2));
          ull x0b = bcast2(xv.x), x1b = bcast2(xv.y);
          const ulonglong2* wv = (const ulonglong2*)(wp + k * (NC1 / 2));
          ulonglong2 wA = wv[0], wB = wv[1];
          asm("fma.rn.f32x2 %0, %1, %2, %0;" : "+l"(acc[0]) : "l"(x0b), "l"(wA.x));
          asm("fma.rn.f32x2 %0, %1, %2, %0;" : "+l"(acc[1]) : "l"(x0b), "l"(wA.y));
          asm("fma.rn.f32x2 %0, %1, %2, %0;" : "+l"(acc[2]) : "l"(x0b), "l"(wB.x));
          asm("fma.rn.f32x2 %0, %1, %2, %0;" : "+l"(acc[3]) : "l"(x0b), "l"(wB.y));
          asm("fma.rn.f32x2 %0, %1, %2, %0;" : "+l"(acc[4]) : "l"(x1b), "l"(wA.x));
          asm("fma.rn.f32x2 %0, %1, %2, %0;" : "+l"(acc[5]) : "l"(x1b), "l"(wA.y));
          asm("fma.rn.f32x2 %0, %1, %2, %0;" : "+l"(acc[6]) : "l"(x1b), "l"(wB.x));
          asm("fma.rn.f32x2 %0, %1, %2, %0;" : "+l"(acc[7]) : "l"(x1b), "l"(wB.y));
        }
      }
      { // store partials: float-idx ks*512 + m*8 + n
        ull* rp = (ull*)(s_red + ks * (Bb * NC1) + m0 * NC1);
        rp[0] = acc[0]; rp[1] = acc[1]; rp[2] = acc[2]; rp[3] = acc[3];
        rp[4] = acc[4]; rp[5] = acc[5]; rp[6] = acc[6]; rp[7] = acc[7];
      }
      __syncthreads();

      { // epilogue: 512 threads -> 64 batch x 8 cols, reduce 16 slices
        int mm = tid & 63, n = tid >> 6;
        float s = s_b1[n];
        #pragma unroll
        for (int q = 0; q < NSL; q++) s += s_red[q * (Bb * NC1) + mm * NC1 + n];
        int c = cid * NC1 + n;
        if (c < Hh) {                                  // f gate -> f*x
          float f  = 1.0f / (1.0f + expf(-s));
          g_xfT[c * Bb + mm] = f * __ldcg(&g_xT[c * Bb + mm]);
        } else if (c < 2 * Hh) {                       // z gate
          g_z[(c - Hh) * Bb + mm] = 1.0f / (1.0f + expf(-s));
        } else {                                       // y readout (pre-update x)
          out[((size_t)mm * Tt + t) * OUTD + (c - 2 * Hh)] = s;
        }
      }
    }
    // ---- barrier 1: release (writers only) + arrive, overlap, wait ----
    if (cid < NCTA2) __threadfence();        // CTAs 128-131 wrote only `out`
    __syncthreads();
    if (tid == 0) atomicAdd(&g_bar, 1u);
    target += NCTA1;

    // overlap: phase-2 u-segment (depends only on g_uT)
    ull acc2[4] = {0ull, 0ull, 0ull, 0ull};  // [m0 c01,c23, m1 c01,c23]
    if (cid < NCTA2) {
      const float2* up = (const float2*)(uT_t + (ks * 4) * Bb + m0);
      const ull*    wp = (const ull*)(s_w2 + (Hh + ks * 4) * NC2);
      #pragma unroll
      for (int k = 0; k < 4; k++) {
        float2 xv = up[k * (Bb / 2)];
        ull x0b = bcast2(xv.x), x1b = bcast2(xv.y);
        ulonglong2 wA = *(const ulonglong2*)(wp + k * (NC2 / 2));
        asm("fma.rn.f32x2 %0, %1, %2, %0;" : "+l"(acc2[0]) : "l"(x0b), "l"(wA.x));
        asm("fma.rn.f32x2 %0, %1, %2, %0;" : "+l"(acc2[1]) : "l"(x0b), "l"(wA.y));
        asm("fma.rn.f32x2 %0, %1, %2, %0;" : "+l"(acc2[2]) : "l"(x1b), "l"(wA.x));
        asm("fma.rn.f32x2 %0, %1, %2, %0;" : "+l"(acc2[3]) : "l"(x1b), "l"(wA.y));
      }
    }
    if (tid == 0) { while (bar_poll() < target) { } }
    __syncthreads();

    // ================= phase 2: r + state update =================
    if (cid < NCTA2) {
      {
        const float2* xp = (const float2*)(g_xfT + (ks * 32) * Bb + m0);
        const ull*    wp = (const ull*)(s_w2 + (ks * 32) * NC2);
        #pragma unroll 8
        for (int k = 0; k < 32; k++) {
          float2 xv = __ldcg(xp + k * (Bb / 2));
          ull x0b = bcast2(xv.x), x1b = bcast2(xv.y);
          ulonglong2 wA = *(const ulonglong2*)(wp + k * (NC2 / 2));
          asm("fma.rn.f32x2 %0, %1, %2, %0;" : "+l"(acc2[0]) : "l"(x0b), "l"(wA.x));
          asm("fma.rn.f32x2 %0, %1, %2, %0;" : "+l"(acc2[1]) : "l"(x0b), "l"(wA.y));
          asm("fma.rn.f32x2 %0, %1, %2, %0;" : "+l"(acc2[2]) : "l"(x1b), "l"(wA.x));
          asm("fma.rn.f32x2 %0, %1, %2, %0;" : "+l"(acc2[3]) : "l"(x1b), "l"(wA.y));
        }
      }
      { // store partials: float-idx ks*256 + m*4 + n
        ull* rp = (ull*)(s_red + ks * (Bb * NC2) + m0 * NC2);
        rp[0] = acc2[0]; rp[1] = acc2[1]; rp[2] = acc2[2]; rp[3] = acc2[3];
      }
      __syncthreads();

      if (tid < 256) {                  // 64 batch x 4 cols, reduce 16 slices
        int mm = tid & 63, n = tid >> 6;
        float s = s_b2[n];
        #pragma unroll
        for (int q = 0; q < NSL; q++) s += s_red[q * (Bb * NC2) + mm * NC2 + n];
        int c = cid * NC2 + n;
        float r  = tanhf(s);
        float z  = __ldcg(&g_z[c * Bb + mm]);
        float xo = __ldcg(&g_xT[c * Bb + mm]);
        g_xT[c * Bb + mm] = (1.0f - z) * xo + z * r;
      }
    }
    // ---- barrier 2: release (writers only) + arrive, overlap, wait ----
    if (cid < NCTA2 && tid < 256) __threadfence();
    __syncthreads();
    if (tid == 0) atomicAdd(&g_bar, 1u);
    target += NCTA1;

    // overlap: phase-1 u-segment for t+1 (clamped; last iter redundant)
    {
      int tn = (t + 1 < Tt) ? (t + 1) : (Tt - 1);
      const float2* up = (const float2*)(g_uT + (size_t)tn * (INx * Bb) + (ks * 4) * Bb + m0);
      const ull*    wp = (const ull*)(s_w1 + (Hh + ks * 4) * NC1);
      #pragma unroll
      for (int p = 0; p < 8; p++) acc1u[p] = 0ull;
      #pragma unroll
      for (int k = 0; k < 4; k++) {
        float2 xv = up[k * (Bb / 2)];
        ull x0b = bcast2(xv.x), x1b = bcast2(xv.y);
        const ulonglong2* wv = (const ulonglong2*)(wp + k * (NC1 / 2));
        ulonglong2 wA = wv[0], wB = wv[1];
        asm("fma.rn.f32x2 %0, %1, %2, %0;" : "+l"(acc1u[0]) : "l"(x0b), "l"(wA.x));
        asm("fma.rn.f32x2 %0, %1, %2, %0;" : "+l"(acc1u[1]) : "l"(x0b), "l"(wA.y));
        asm("fma.rn.f32x2 %0, %1, %2, %0;" : "+l"(acc1u[2]) : "l"(x0b), "l"(wB.x));
        asm("fma.rn.f32x2 %0, %1, %2, %0;" : "+l"(acc1u[3]) : "l"(x0b), "l"(wB.y));
        asm("fma.rn.f32x2 %0, %1, %2, %0;" : "+l"(acc1u[4]) : "l"(x1b), "l"(wA.x));
        asm("fma.rn.f32x2 %0, %1, %2, %0;" : "+l"(acc1u[5]) : "l"(x1b), "l"(wA.y));
        asm("fma.rn.f32x2 %0, %1, %2, %0;" : "+l"(acc1u[6]) : "l"(x1b), "l"(wB.x));
        asm("fma.rn.f32x2 %0, %1, %2, %0;" : "+l"(acc1u[7]) : "l"(x1b), "l"(wB.y));
      }
    }
    if (tid == 0) { while (bar_poll() < target) { } }
    __syncthreads();
  }
}

// Trailing reset: runs AFTER gru_main each launch, restoring g_bar = 0 for the
// next replay (first-ever launch uses the static initializer).
__global__ void zero_bar_kernel() { g_bar = 0u; }

extern "C" void kernel_launch(void* const* d_in, const int* in_sizes, int n_in,
                              void* d_out, int out_size) {
  // Resolve inputs by UNIQUE element counts (immune to metadata ordering).
  const float *u = 0, *x0 = 0, *kernel_fz = 0, *bias_fz = 0,
              *kernel_r = 0, *bias_r = 0, *W_out = 0, *b_out = 0;
  for (int i = 0; i < n_in; i++) {
    const float* p = (const float*)d_in[i];
    switch (in_sizes[i]) {
      case 8388608: u         = p; break;  // 64*2048*64
      case 32768:   x0        = p; break;  // 64*1*512
      case 589824:  kernel_fz = p; break;  // 576*1024
      case 1024:    bias_fz   = p; break;
      case 294912:  kernel_r  = p; break;  // 576*512
      case 512:     bias_r    = p; break;
      case 16384:   W_out     = p; break;  // 32*512
      case 32:      b_out     = p; break;
      default: break;
    }
  }
  if (!u || !x0 || !kernel_fz || !bias_fz || !kernel_r || !bias_r || !W_out || !b_out) {
    u         = (const float*)d_in[0];
    x0        = (const float*)d_in[1];
    kernel_fz = (const float*)d_in[2];
    bias_fz   = (const float*)d_in[3];
    kernel_r  = (const float*)d_in[4];
    bias_r    = (const float*)d_in[5];
    W_out     = (const float*)d_in[6];
    b_out     = (const float*)d_in[7];
  }
  float* out = (float*)d_out;

  static int smem_set = 0;
  if (!smem_set) {
    cudaFuncSetAttribute(gru_main, cudaFuncAttributeMaxDynamicSharedMemorySize,
                         SMEM_BYTES);
    smem_set = 1;
  }

  void* args[] = { (void*)&u, (void*)&x0,
                   (void*)&kernel_fz, (void*)&bias_fz, (void*)&kernel_r,
                   (void*)&bias_r,    (void*)&W_out,   (void*)&b_out,
                   (void*)&out };
  cudaLaunchCooperativeKernel((const void*)gru_main, dim3(NCTA1), dim3(NTHR),
                              args, SMEM_BYTES, (cudaStream_t)0);
  zero_bar_kernel<<<1, 1>>>();
}

// round 10
// speedup vs baseline: 1.6396x; 1.2303x over previous
#include <cuda_runtime.h>
#include <math.h>
#include <stdint.h>

// Problem dims
#define Bb   64
#define Tt   2048
#define INx  64
#define Hh   512
#define OUTD 32
#define K1   576      // INx + Hh
#define NCTA1 132     // 132*8 = 1056 = 1024 fz cols + 32 y cols
#define NC1  8        // phase-1 cols per CTA
#define NCTA2 128     // 128*4 = 512 r cols
#define NC2  4        // phase-2 cols per CTA
#define NTHR 512
#define NSL  16       // K-slices = warps; each warp owns 32 x-rows + 4 u-rows; lane = m-pair

typedef unsigned long long ull;

// ---- persistent device scratch (no allocation allowed) ----
__device__ float g_xT [Hh * Bb];               // state, transposed [k][m]
__device__ float g_xfT[Hh * Bb];               // f*x, transposed  [k][m]
__device__ float g_z  [Hh * Bb];               // z gate           [j][m]
__device__ float g_uT [(size_t)Tt * INx * Bb]; // u transposed: [t][i][m]  (32 MB)
__device__ unsigned g_bar;                     // zeroed by zero_bar_kernel BEFORE gru_main

// SMEM layout (floats) in dynamic shared memory
#define OFF_W1  0                    // 576*8  = 4608
#define OFF_W2  4608                 // 576*4  = 2304
#define OFF_RED 6912                 // 16*8*64 = 8192 (also reused as transpose tile)
#define OFF_B1  15104                // 8
#define OFF_B2  15112                // 8 (4 used)
#define SMEM_FLOATS 15120
#define SMEM_BYTES  (SMEM_FLOATS * 4)

__device__ __forceinline__ ull bcast2(float v) {
  ull r;
  asm("mov.b64 %0, {%1, %1};" : "=l"(r) : "r"(__float_as_uint(v)));
  return r;
}
__device__ __forceinline__ unsigned bar_poll() {
  unsigned v;
  asm volatile("ld.acquire.gpu.global.u32 %0, [%1];" : "=r"(v) : "l"(&g_bar) : "memory");
  return v;
}
// Unpack a f32x2 accumulator into (lo, hi) floats
__device__ __forceinline__ void unpack2(ull a, float& lo, float& hi) {
  unsigned l, h;
  asm("mov.b64 {%0,%1}, %2;" : "=r"(l), "=r"(h) : "l"(a));
  lo = __uint_as_float(l); hi = __uint_as_float(h);
}

__global__ void __launch_bounds__(NTHR, 1) gru_main(
    const float* __restrict__ u,
    const float* __restrict__ x0,
    const float* __restrict__ kernel_fz, const float* __restrict__ bias_fz,
    const float* __restrict__ kernel_r,  const float* __restrict__ bias_r,
    const float* __restrict__ W_out,     const float* __restrict__ b_out,
    float* __restrict__ out)
{
  extern __shared__ float smem[];
  float* s_w1  = smem + OFF_W1;   // [kk][n], kk 0..511 = x rows, 512..575 = u rows
  float* s_w2  = smem + OFF_W2;
  float* s_red = smem + OFF_RED;  // [ks][n][m] — conflict-free layout
  float* s_b1  = smem + OFF_B1;
  float* s_b2  = smem + OFF_B2;

  const int tid = threadIdx.x;
  const int cid = blockIdx.x;
  const int mg  = tid & 31;    // m-pair group: handles batch rows 2mg, 2mg+1
  const int ks  = tid >> 5;    // K-slice 0..15 (= warp id)
  const int m0  = 2 * mg;

  unsigned target = 0;

  // ---- stationary weight slices into SMEM ----
  for (int i = tid; i < K1 * NC1; i += NTHR) {
    int kk = i / NC1, n = i % NC1;
    int c  = cid * NC1 + n;
    int row = (kk < Hh) ? (INx + kk) : (kk - Hh);   // concat order: [u | x]
    float w;
    if (c < 2 * Hh) w = kernel_fz[row * (2 * Hh) + c];
    else { int o = c - 2 * Hh; w = (kk < Hh) ? W_out[o * Hh + kk] : 0.0f; }
    s_w1[i] = w;
  }
  if (cid < NCTA2) {
    for (int i = tid; i < K1 * NC2; i += NTHR) {
      int kk = i / NC2, n = i % NC2;
      int j  = cid * NC2 + n;
      int row = (kk < Hh) ? (INx + kk) : (kk - Hh);
      s_w2[i] = kernel_r[row * Hh + j];
    }
  }
  if (tid < NC1) {
    int c = cid * NC1 + tid;
    s_b1[tid] = (c < 2 * Hh) ? bias_fz[c] : b_out[c - 2 * Hh];
  }
  if (cid < NCTA2 && tid < NC2) s_b2[tid] = bias_r[cid * NC2 + tid];

  // ---- in-kernel init: x0 -> g_xT (grid-stride) ----
  for (int idx = cid * NTHR + tid; idx < Hh * Bb; idx += NCTA1 * NTHR) {
    int k = idx >> 6, mm = idx & 63;
    g_xT[idx] = x0[mm * Hh + k];          // x0 is (64, 1, 512)
  }

  // ---- in-kernel u transpose: u(B,T,IN) -> g_uT[t][i][m] ----
  {
    float* tile = s_red;                  // 64*65 = 4160 floats, fits in RED region
    __syncthreads();
    for (int t = cid; t < Tt; t += NCTA1) {
      for (int idx = tid; idx < INx * Bb; idx += NTHR) {
        int mm = idx >> 6, i = idx & 63;  // coalesced read over i
        tile[mm * 65 + i] = u[((size_t)mm * Tt + t) * INx + i];
      }
      __syncthreads();
      for (int idx = tid; idx < INx * Bb; idx += NTHR) {
        g_uT[(size_t)t * (INx * Bb) + idx] = tile[(idx & 63) * 65 + (idx >> 6)];
      }
      __syncthreads();
    }
  }

  // ---- grid barrier after init/transpose ----
  __threadfence();
  __syncthreads();
  if (tid == 0) atomicAdd(&g_bar, 1u);
  target += NCTA1;
  if (tid == 0) { while (bar_poll() < target) { } }
  __syncthreads();

  // ---- prologue: phase-1 u-segment for t = 0 ----
  ull acc1u[NC1];    // [0..3] = m0 col-pairs, [4..7] = m1 col-pairs
  {
    #pragma unroll
    for (int p = 0; p < 8; p++) acc1u[p] = 0ull;
    const float2* up = (const float2*)(g_uT + (ks * 4) * Bb + m0);
    const ull*    wp = (const ull*)(s_w1 + (Hh + ks * 4) * NC1);
    #pragma unroll
    for (int k = 0; k < 4; k++) {
      float2 xv = up[k * (Bb / 2)];
      ull x0b = bcast2(xv.x), x1b = bcast2(xv.y);
      const ulonglong2* wv = (const ulonglong2*)(wp + k * (NC1 / 2));
      ulonglong2 wA = wv[0], wB = wv[1];
      asm("fma.rn.f32x2 %0, %1, %2, %0;" : "+l"(acc1u[0]) : "l"(x0b), "l"(wA.x));
      asm("fma.rn.f32x2 %0, %1, %2, %0;" : "+l"(acc1u[1]) : "l"(x0b), "l"(wA.y));
      asm("fma.rn.f32x2 %0, %1, %2, %0;" : "+l"(acc1u[2]) : "l"(x0b), "l"(wB.x));
      asm("fma.rn.f32x2 %0, %1, %2, %0;" : "+l"(acc1u[3]) : "l"(x0b), "l"(wB.y));
      asm("fma.rn.f32x2 %0, %1, %2, %0;" : "+l"(acc1u[4]) : "l"(x1b), "l"(wA.x));
      asm("fma.rn.f32x2 %0, %1, %2, %0;" : "+l"(acc1u[5]) : "l"(x1b), "l"(wA.y));
      asm("fma.rn.f32x2 %0, %1, %2, %0;" : "+l"(acc1u[6]) : "l"(x1b), "l"(wB.x));
      asm("fma.rn.f32x2 %0, %1, %2, %0;" : "+l"(acc1u[7]) : "l"(x1b), "l"(wB.y));
    }
  }

  for (int t = 0; t < Tt; t++) {
    const float* uT_t = g_uT + (size_t)t * (INx * Bb);

    // ================= phase 1: fz logits + y readout =================
    {
      ull acc[8];
      #pragma unroll
      for (int p = 0; p < 8; p++) acc[p] = acc1u[p];

      { // x segment: rows [ks*32, ks*32+32)
        const float2* xp = (const float2*)(g_xT + (ks * 32) * Bb + m0);
        const ull*    wp = (const ull*)(s_w1 + (ks * 32) * NC1);
        #pragma unroll 8
        for (int k = 0; k < 32; k++) {
          float2 xv = __ldcg(xp + k * (Bb / 2));
          ull x0b = bcast2(xv.x), x1b = bcast2(xv.y);
          const ulonglong2* wv = (const ulonglong2*)(wp + k * (NC1 / 2));
          ulonglong2 wA = wv[0], wB = wv[1];
          asm("fma.rn.f32x2 %0, %1, %2, %0;" : "+l"(acc[0]) : "l"(x0b), "l"(wA.x));
          asm("fma.rn.f32x2 %0, %1, %2, %0;" : "+l"(acc[1]) : "l"(x0b), "l"(wA.y));
          asm("fma.rn.f32x2 %0, %1, %2, %0;" : "+l"(acc[2]) : "l"(x0b), "l"(wB.x));
          asm("fma.rn.f32x2 %0, %1, %2, %0;" : "+l"(acc[3]) : "l"(x0b), "l"(wB.y));
          asm("fma.rn.f32x2 %0, %1, %2, %0;" : "+l"(acc[4]) : "l"(x1b), "l"(wA.x));
          asm("fma.rn.f32x2 %0, %1, %2, %0;" : "+l"(acc[5]) : "l"(x1b), "l"(wA.y));
          asm("fma.rn.f32x2 %0, %1, %2, %0;" : "+l"(acc[6]) : "l"(x1b), "l"(wB.x));
          asm("fma.rn.f32x2 %0, %1, %2, %0;" : "+l"(acc[7]) : "l"(x1b), "l"(wB.y));
        }
      }
      { // store partials, layout [ks][n][m]: float2(m0,m1) per column.
        // lane byte-offset = 8*mg -> consecutive 8B -> conflict-free STS.64
        float* rp = s_red + ks * (NC1 * Bb);
        #pragma unroll
        for (int p = 0; p < 4; p++) {
          float e0, o0, e1, o1;
          unpack2(acc[p],     e0, o0);   // m0: col 2p, col 2p+1
          unpack2(acc[4 + p], e1, o1);   // m1
          float2 ve; ve.x = e0; ve.y = e1;
          float2 vo; vo.x = o0; vo.y = o1;
          *(float2*)(rp + (2 * p)     * Bb + m0) = ve;
          *(float2*)(rp + (2 * p + 1) * Bb + m0) = vo;
        }
      }
      __syncthreads();

      { // epilogue: 512 threads -> 64 batch x 8 cols; conflict-free LDS
        int mm = tid & 63, n = tid >> 6;
        float s = s_b1[n];
        #pragma unroll
        for (int q = 0; q < NSL; q++) s += s_red[q * (NC1 * Bb) + n * Bb + mm];
        int c = cid * NC1 + n;
        if (c < Hh) {                                  // f gate -> f*x
          float f  = 1.0f / (1.0f + expf(-s));
          g_xfT[c * Bb + mm] = f * __ldcg(&g_xT[c * Bb + mm]);
        } else if (c < 2 * Hh) {                       // z gate
          g_z[(c - Hh) * Bb + mm] = 1.0f / (1.0f + expf(-s));
        } else {                                       // y readout (pre-update x)
          out[((size_t)mm * Tt + t) * OUTD + (c - 2 * Hh)] = s;
        }
      }
    }
    // ---- barrier 1: release (writers only) + arrive, overlap, wait ----
    if (cid < NCTA2) __threadfence();        // CTAs 128-131 wrote only `out`
    __syncthreads();
    if (tid == 0) atomicAdd(&g_bar, 1u);
    target += NCTA1;

    // overlap: phase-2 u-segment (depends only on g_uT)
    ull acc2[4] = {0ull, 0ull, 0ull, 0ull};  // [0..1] m0 col-pairs, [2..3] m1
    if (cid < NCTA2) {
      const float2* up = (const float2*)(uT_t + (ks * 4) * Bb + m0);
      const ull*    wp = (const ull*)(s_w2 + (Hh + ks * 4) * NC2);
      #pragma unroll
      for (int k = 0; k < 4; k++) {
        float2 xv = up[k * (Bb / 2)];
        ull x0b = bcast2(xv.x), x1b = bcast2(xv.y);
        ulonglong2 wA = *(const ulonglong2*)(wp + k * (NC2 / 2));
        asm("fma.rn.f32x2 %0, %1, %2, %0;" : "+l"(acc2[0]) : "l"(x0b), "l"(wA.x));
        asm("fma.rn.f32x2 %0, %1, %2, %0;" : "+l"(acc2[1]) : "l"(x0b), "l"(wA.y));
        asm("fma.rn.f32x2 %0, %1, %2, %0;" : "+l"(acc2[2]) : "l"(x1b), "l"(wA.x));
        asm("fma.rn.f32x2 %0, %1, %2, %0;" : "+l"(acc2[3]) : "l"(x1b), "l"(wA.y));
      }
    }
    if (tid == 0) { while (bar_poll() < target) { } }
    __syncthreads();

    // ================= phase 2: r + state update =================
    if (cid < NCTA2) {
      {
        const float2* xp = (const float2*)(g_xfT + (ks * 32) * Bb + m0);
        const ull*    wp = (const ull*)(s_w2 + (ks * 32) * NC2);
        #pragma unroll 8
        for (int k = 0; k < 32; k++) {
          float2 xv = __ldcg(xp + k * (Bb / 2));
          ull x0b = bcast2(xv.x), x1b = bcast2(xv.y);
          ulonglong2 wA = *(const ulonglong2*)(wp + k * (NC2 / 2));
          asm("fma.rn.f32x2 %0, %1, %2, %0;" : "+l"(acc2[0]) : "l"(x0b), "l"(wA.x));
          asm("fma.rn.f32x2 %0, %1, %2, %0;" : "+l"(acc2[1]) : "l"(x0b), "l"(wA.y));
          asm("fma.rn.f32x2 %0, %1, %2, %0;" : "+l"(acc2[2]) : "l"(x1b), "l"(wA.x));
          asm("fma.rn.f32x2 %0, %1, %2, %0;" : "+l"(acc2[3]) : "l"(x1b), "l"(wA.y));
        }
      }
      { // store partials, layout [ks][n][m], conflict-free
        float* rp = s_red + ks * (NC2 * Bb);
        #pragma unroll
        for (int p = 0; p < 2; p++) {
          float e0, o0, e1, o1;
          unpack2(acc2[p],     e0, o0);
          unpack2(acc2[2 + p], e1, o1);
          float2 ve; ve.x = e0; ve.y = e1;
          float2 vo; vo.x = o0; vo.y = o1;
          *(float2*)(rp + (2 * p)     * Bb + m0) = ve;
          *(float2*)(rp + (2 * p + 1) * Bb + m0) = vo;
        }
      }
      __syncthreads();

      if (tid < 256) {                  // 64 batch x 4 cols; conflict-free LDS
        int mm = tid & 63, n = tid >> 6;
        float s = s_b2[n];
        #pragma unroll
        for (int q = 0; q < NSL; q++) s += s_red[q * (NC2 * Bb) + n * Bb + mm];
        int c = cid * NC2 + n;
        float r  = tanhf(s);
        float z  = __ldcg(&g_z[c * Bb + mm]);
        float xo = __ldcg(&g_xT[c * Bb + mm]);
        g_xT[c * Bb + mm] = (1.0f - z) * xo + z * r;
      }
    }
    // ---- barrier 2: release (writers only) + arrive, overlap, wait ----
    if (cid < NCTA2 && tid < 256) __threadfence();
    __syncthreads();
    if (tid == 0) atomicAdd(&g_bar, 1u);
    target += NCTA1;

    // overlap: phase-1 u-segment for t+1 (clamped; last iter redundant)
    {
      int tn = (t + 1 < Tt) ? (t + 1) : (Tt - 1);
      const float2* up = (const float2*)(g_uT + (size_t)tn * (INx * Bb) + (ks * 4) * Bb + m0);
      const ull*    wp = (const ull*)(s_w1 + (Hh + ks * 4) * NC1);
      #pragma unroll
      for (int p = 0; p < 8; p++) acc1u[p] = 0ull;
      #pragma unroll
      for (int k = 0; k < 4; k++) {
        float2 xv = up[k * (Bb / 2)];
        ull x0b = bcast2(xv.x), x1b = bcast2(xv.y);
        const ulonglong2* wv = (const ulonglong2*)(wp + k * (NC1 / 2));
        ulonglong2 wA = wv[0], wB = wv[1];
        asm("fma.rn.f32x2 %0, %1, %2, %0;" : "+l"(acc1u[0]) : "l"(x0b), "l"(wA.x));
        asm("fma.rn.f32x2 %0, %1, %2, %0;" : "+l"(acc1u[1]) : "l"(x0b), "l"(wA.y));
        asm("fma.rn.f32x2 %0, %1, %2, %0;" : "+l"(acc1u[2]) : "l"(x0b), "l"(wB.x));
        asm("fma.rn.f32x2 %0, %1, %2, %0;" : "+l"(acc1u[3]) : "l"(x0b), "l"(wB.y));
        asm("fma.rn.f32x2 %0, %1, %2, %0;" : "+l"(acc1u[4]) : "l"(x1b), "l"(wA.x));
        asm("fma.rn.f32x2 %0, %1, %2, %0;" : "+l"(acc1u[5]) : "l"(x1b), "l"(wA.y));
        asm("fma.rn.f32x2 %0, %1, %2, %0;" : "+l"(acc1u[6]) : "l"(x1b), "l"(wB.x));
        asm("fma.rn.f32x2 %0, %1, %2, %0;" : "+l"(acc1u[7]) : "l"(x1b), "l"(wB.y));
      }
    }
    if (tid == 0) { while (bar_poll() < target) { } }
    __syncthreads();
  }
}

// Runs BEFORE gru_main each invocation: resets the barrier counter and shifts
// launch parity so ncu (-s 5 -c 1) captures gru_main as launch #6.
__global__ void zero_bar_kernel() { g_bar = 0u; }

extern "C" void kernel_launch(void* const* d_in, const int* in_sizes, int n_in,
                              void* d_out, int out_size) {
  // Resolve inputs by UNIQUE element counts (immune to metadata ordering).
  const float *u = 0, *x0 = 0, *kernel_fz = 0, *bias_fz = 0,
              *kernel_r = 0, *bias_r = 0, *W_out = 0, *b_out = 0;
  for (int i = 0; i < n_in; i++) {
    const float* p = (const float*)d_in[i];
    switch (in_sizes[i]) {
      case 8388608: u         = p; break;  // 64*2048*64
      case 32768:   x0        = p; break;  // 64*1*512
      case 589824:  kernel_fz = p; break;  // 576*1024
      case 1024:    bias_fz   = p; break;
      case 294912:  kernel_r  = p; break;  // 576*512
      case 512:     bias_r    = p; break;
      case 16384:   W_out     = p; break;  // 32*512
      case 32:      b_out     = p; break;
      default: break;
    }
  }
  if (!u || !x0 || !kernel_fz || !bias_fz || !kernel_r || !bias_r || !W_out || !b_out) {
    u         = (const float*)d_in[0];
    x0        = (const float*)d_in[1];
    kernel_fz = (const float*)d_in[2];
    bias_fz   = (const float*)d_in[3];
    kernel_r  = (const float*)d_in[4];
    bias_r    = (const float*)d_in[5];
    W_out     = (const float*)d_in[6];
    b_out     = (const float*)d_in[7];
  }
  float* out = (float*)d_out;

  static int smem_set = 0;
  if (!smem_set) {
    cudaFuncSetAttribute(gru_main, cudaFuncAttributeMaxDynamicSharedMemorySize,
                         SMEM_BYTES);
    smem_set = 1;
  }

  zero_bar_kernel<<<1, 1>>>();

  void* args[] = { (void*)&u, (void*)&x0,
                   (void*)&kernel_fz, (void*)&bias_fz, (void*)&kernel_r,
                   (void*)&bias_r,    (void*)&W_out,   (void*)&b_out,
                   (void*)&out };
  cudaLaunchCooperativeKernel((const void*)gru_main, dim3(NCTA1), dim3(NTHR),
                              args, SMEM_BYTES, (cudaStream_t)0);
}

// round 11
// speedup vs baseline: 1.6849x; 1.0277x over previous
#include <cuda_runtime.h>
#include <math.h>
#include <stdint.h>

// Problem dims
#define Bb   64
#define Tt   2048
#define INx  64
#define Hh   512
#define OUTD 32
#define K1   576      // INx + Hh
#define NCTA1 132     // 132*8 = 1056 = 1024 fz cols + 32 y cols
#define NC1  8        // phase-1 cols per CTA
#define NCTA2 128     // 128*4 = 512 r cols
#define NC2  4        // phase-2 cols per CTA
#define NTHR 512
#define NSL  16       // K-slices = warps; each warp owns 32 x-rows + 4 u-rows; lane = m-pair

typedef unsigned long long ull;

// ---- persistent device scratch (no allocation allowed) ----
__device__ float g_xT [Hh * Bb];               // state, transposed [k][m]
__device__ float g_xfT[Hh * Bb];               // f*x, transposed  [k][m]
__device__ float g_z  [Hh * Bb];               // z gate           [j][m]
__device__ float g_uT [(size_t)Tt * INx * Bb]; // u transposed: [t][i][m]  (32 MB)
__device__ unsigned g_bar;                     // zeroed by zero_bar_kernel BEFORE gru_main

// SMEM layout (floats) in dynamic shared memory
#define OFF_W1  0                    // 576*8  = 4608
#define OFF_W2  4608                 // 576*4  = 2304
#define OFF_RED 6912                 // 16*8*64 = 8192 (also reused as transpose tile)
#define OFF_B1  15104                // 8
#define OFF_B2  15112                // 8 (4 used)
#define SMEM_FLOATS 15120
#define SMEM_BYTES  (SMEM_FLOATS * 4)

__device__ __forceinline__ ull bcast2(float v) {
  ull r;
  asm("mov.b64 %0, {%1, %1};" : "=l"(r) : "r"(__float_as_uint(v)));
  return r;
}
__device__ __forceinline__ unsigned bar_poll() {
  unsigned v;
  asm volatile("ld.acquire.gpu.global.u32 %0, [%1];" : "=r"(v) : "l"(&g_bar) : "memory");
  return v;
}
// Unpack a f32x2 accumulator into (lo, hi) floats
__device__ __forceinline__ void unpack2(ull a, float& lo, float& hi) {
  unsigned l, h;
  asm("mov.b64 {%0,%1}, %2;" : "=r"(l), "=r"(h) : "l"(a));
  lo = __uint_as_float(l); hi = __uint_as_float(h);
}

__global__ void __launch_bounds__(NTHR, 1) gru_main(
    const float* __restrict__ u,
    const float* __restrict__ x0,
    const float* __restrict__ kernel_fz, const float* __restrict__ bias_fz,
    const float* __restrict__ kernel_r,  const float* __restrict__ bias_r,
    const float* __restrict__ W_out,     const float* __restrict__ b_out,
    float* __restrict__ out)
{
  extern __shared__ float smem[];
  float* s_w1  = smem + OFF_W1;   // [kk][n], kk 0..511 = x rows, 512..575 = u rows
  float* s_w2  = smem + OFF_W2;
  float* s_red = smem + OFF_RED;  // [ks][n][m] — conflict-free layout
  float* s_b1  = smem + OFF_B1;
  float* s_b2  = smem + OFF_B2;

  const int tid = threadIdx.x;
  const int cid = blockIdx.x;
  const int mg  = tid & 31;    // m-pair group: handles batch rows 2mg, 2mg+1
  const int ks  = tid >> 5;    // K-slice 0..15 (= warp id)
  const int m0  = 2 * mg;

  unsigned target = 0;

  // ---- stationary weight slices into SMEM ----
  for (int i = tid; i < K1 * NC1; i += NTHR) {
    int kk = i / NC1, n = i % NC1;
    int c  = cid * NC1 + n;
    int row = (kk < Hh) ? (INx + kk) : (kk - Hh);   // concat order: [u | x]
    float w;
    if (c < 2 * Hh) w = kernel_fz[row * (2 * Hh) + c];
    else { int o = c - 2 * Hh; w = (kk < Hh) ? W_out[o * Hh + kk] : 0.0f; }
    s_w1[i] = w;
  }
  if (cid < NCTA2) {
    for (int i = tid; i < K1 * NC2; i += NTHR) {
      int kk = i / NC2, n = i % NC2;
      int j  = cid * NC2 + n;
      int row = (kk < Hh) ? (INx + kk) : (kk - Hh);
      s_w2[i] = kernel_r[row * Hh + j];
    }
  }
  if (tid < NC1) {
    int c = cid * NC1 + tid;
    s_b1[tid] = (c < 2 * Hh) ? bias_fz[c] : b_out[c - 2 * Hh];
  }
  if (cid < NCTA2 && tid < NC2) s_b2[tid] = bias_r[cid * NC2 + tid];

  // ---- in-kernel init: x0 -> g_xT (grid-stride) ----
  for (int idx = cid * NTHR + tid; idx < Hh * Bb; idx += NCTA1 * NTHR) {
    int k = idx >> 6, mm = idx & 63;
    g_xT[idx] = x0[mm * Hh + k];          // x0 is (64, 1, 512)
  }

  // ---- in-kernel u transpose: u(B,T,IN) -> g_uT[t][i][m] ----
  {
    float* tile = s_red;                  // 64*65 = 4160 floats, fits in RED region
    __syncthreads();
    for (int t = cid; t < Tt; t += NCTA1) {
      for (int idx = tid; idx < INx * Bb; idx += NTHR) {
        int mm = idx >> 6, i = idx & 63;  // coalesced read over i
        tile[mm * 65 + i] = u[((size_t)mm * Tt + t) * INx + i];
      }
      __syncthreads();
      for (int idx = tid; idx < INx * Bb; idx += NTHR) {
        g_uT[(size_t)t * (INx * Bb) + idx] = tile[(idx & 63) * 65 + (idx >> 6)];
      }
      __syncthreads();
    }
  }

  // ---- grid barrier after init/transpose ----
  __threadfence();
  __syncthreads();
  if (tid == 0) atomicAdd(&g_bar, 1u);
  target += NCTA1;
  if (tid == 0) { while (bar_poll() < target) { } }
  __syncthreads();

  // ---- prologue: phase-1 u-segment for t = 0 ----
  ull acc1u[NC1];    // [0..3] = m0 col-pairs, [4..7] = m1 col-pairs
  {
    #pragma unroll
    for (int p = 0; p < 8; p++) acc1u[p] = 0ull;
    const float2* up = (const float2*)(g_uT + (ks * 4) * Bb + m0);
    const ull*    wp = (const ull*)(s_w1 + (Hh + ks * 4) * NC1);
    #pragma unroll
    for (int k = 0; k < 4; k++) {
      float2 xv = up[k * (Bb / 2)];
      ull x0b = bcast2(xv.x), x1b = bcast2(xv.y);
      const ulonglong2* wv = (const ulonglong2*)(wp + k * (NC1 / 2));
      ulonglong2 wA = wv[0], wB = wv[1];
      asm("fma.rn.f32x2 %0, %1, %2, %0;" : "+l"(acc1u[0]) : "l"(x0b), "l"(wA.x));
      asm("fma.rn.f32x2 %0, %1, %2, %0;" : "+l"(acc1u[1]) : "l"(x0b), "l"(wA.y));
      asm("fma.rn.f32x2 %0, %1, %2, %0;" : "+l"(acc1u[2]) : "l"(x0b), "l"(wB.x));
      asm("fma.rn.f32x2 %0, %1, %2, %0;" : "+l"(acc1u[3]) : "l"(x0b), "l"(wB.y));
      asm("fma.rn.f32x2 %0, %1, %2, %0;" : "+l"(acc1u[4]) : "l"(x1b), "l"(wA.x));
      asm("fma.rn.f32x2 %0, %1, %2, %0;" : "+l"(acc1u[5]) : "l"(x1b), "l"(wA.y));
      asm("fma.rn.f32x2 %0, %1, %2, %0;" : "+l"(acc1u[6]) : "l"(x1b), "l"(wB.x));
      asm("fma.rn.f32x2 %0, %1, %2, %0;" : "+l"(acc1u[7]) : "l"(x1b), "l"(wB.y));
    }
  }

  for (int t = 0; t < Tt; t++) {
    const float* uT_t = g_uT + (size_t)t * (INx * Bb);

    // ================= phase 1: fz logits + y readout =================
    {
      ull acc[8];
      #pragma unroll
      for (int p = 0; p < 8; p++) acc[p] = acc1u[p];

      { // x segment: rows [ks*32, ks*32+32), 2-stage register staging (MLP~16)
        const float2* xp = (const float2*)(g_xT + (ks * 32) * Bb + m0);
        const ull*    wp = (const ull*)(s_w1 + (ks * 32) * NC1);
        float2 buf[8];
        #pragma unroll
        for (int j = 0; j < 8; j++) buf[j] = __ldcg(xp + j * (Bb / 2));
        #pragma unroll
        for (int blk = 0; blk < 4; blk++) {
          float2 nbuf[8];
          if (blk < 3) {
            #pragma unroll
            for (int j = 0; j < 8; j++)
              nbuf[j] = __ldcg(xp + ((blk + 1) * 8 + j) * (Bb / 2));
          }
          #pragma unroll
          for (int j = 0; j < 8; j++) {
            int k = blk * 8 + j;
            ull x0b = bcast2(buf[j].x), x1b = bcast2(buf[j].y);
            const ulonglong2* wv = (const ulonglong2*)(wp + k * (NC1 / 2));
            ulonglong2 wA = wv[0], wB = wv[1];
            asm("fma.rn.f32x2 %0, %1, %2, %0;" : "+l"(acc[0]) : "l"(x0b), "l"(wA.x));
            asm("fma.rn.f32x2 %0, %1, %2, %0;" : "+l"(acc[1]) : "l"(x0b), "l"(wA.y));
            asm("fma.rn.f32x2 %0, %1, %2, %0;" : "+l"(acc[2]) : "l"(x0b), "l"(wB.x));
            asm("fma.rn.f32x2 %0, %1, %2, %0;" : "+l"(acc[3]) : "l"(x0b), "l"(wB.y));
            asm("fma.rn.f32x2 %0, %1, %2, %0;" : "+l"(acc[4]) : "l"(x1b), "l"(wA.x));
            asm("fma.rn.f32x2 %0, %1, %2, %0;" : "+l"(acc[5]) : "l"(x1b), "l"(wA.y));
            asm("fma.rn.f32x2 %0, %1, %2, %0;" : "+l"(acc[6]) : "l"(x1b), "l"(wB.x));
            asm("fma.rn.f32x2 %0, %1, %2, %0;" : "+l"(acc[7]) : "l"(x1b), "l"(wB.y));
          }
          #pragma unroll
          for (int j = 0; j < 8; j++) buf[j] = nbuf[j];
        }
      }
      { // store partials, layout [ks][n][m]: float2(m0,m1) per column — conflict-free STS.64
        float* rp = s_red + ks * (NC1 * Bb);
        #pragma unroll
        for (int p = 0; p < 4; p++) {
          float e0, o0, e1, o1;
          unpack2(acc[p],     e0, o0);   // m0: col 2p, col 2p+1
          unpack2(acc[4 + p], e1, o1);   // m1
          float2 ve; ve.x = e0; ve.y = e1;
          float2 vo; vo.x = o0; vo.y = o1;
          *(float2*)(rp + (2 * p)     * Bb + m0) = ve;
          *(float2*)(rp + (2 * p + 1) * Bb + m0) = vo;
        }
      }
      __syncthreads();

      { // epilogue: 512 threads -> 64 batch x 8 cols; conflict-free LDS
        int mm = tid & 63, n = tid >> 6;
        float s = s_b1[n];
        #pragma unroll
        for (int q = 0; q < NSL; q++) s += s_red[q * (NC1 * Bb) + n * Bb + mm];
        int c = cid * NC1 + n;
        if (c < Hh) {                                  // f gate -> f*x
          float f  = 1.0f / (1.0f + expf(-s));
          g_xfT[c * Bb + mm] = f * __ldcg(&g_xT[c * Bb + mm]);
        } else if (c < 2 * Hh) {                       // z gate
          g_z[(c - Hh) * Bb + mm] = 1.0f / (1.0f + expf(-s));
        } else {                                       // y readout (pre-update x)
          out[((size_t)mm * Tt + t) * OUTD + (c - 2 * Hh)] = s;
        }
      }
    }
    // ---- barrier 1: release (writers only) + arrive, overlap, wait ----
    if (cid < NCTA2) __threadfence();        // CTAs 128-131 wrote only `out`
    __syncthreads();
    if (tid == 0) atomicAdd(&g_bar, 1u);
    target += NCTA1;

    // overlap: phase-2 u-segment (depends only on g_uT)
    ull acc2[4] = {0ull, 0ull, 0ull, 0ull};  // [0..1] m0 col-pairs, [2..3] m1
    if (cid < NCTA2) {
      const float2* up = (const float2*)(uT_t + (ks * 4) * Bb + m0);
      const ull*    wp = (const ull*)(s_w2 + (Hh + ks * 4) * NC2);
      #pragma unroll
      for (int k = 0; k < 4; k++) {
        float2 xv = up[k * (Bb / 2)];
        ull x0b = bcast2(xv.x), x1b = bcast2(xv.y);
        ulonglong2 wA = *(const ulonglong2*)(wp + k * (NC2 / 2));
        asm("fma.rn.f32x2 %0, %1, %2, %0;" : "+l"(acc2[0]) : "l"(x0b), "l"(wA.x));
        asm("fma.rn.f32x2 %0, %1, %2, %0;" : "+l"(acc2[1]) : "l"(x0b), "l"(wA.y));
        asm("fma.rn.f32x2 %0, %1, %2, %0;" : "+l"(acc2[2]) : "l"(x1b), "l"(wA.x));
        asm("fma.rn.f32x2 %0, %1, %2, %0;" : "+l"(acc2[3]) : "l"(x1b), "l"(wA.y));
      }
    }
    if (tid == 0) { while (bar_poll() < target) { } }
    __syncthreads();

    // ================= phase 2: r + state update =================
    if (cid < NCTA2) {
      { // x segment with 2-stage register staging
        const float2* xp = (const float2*)(g_xfT + (ks * 32) * Bb + m0);
        const ull*    wp = (const ull*)(s_w2 + (ks * 32) * NC2);
        float2 buf[8];
        #pragma unroll
        for (int j = 0; j < 8; j++) buf[j] = __ldcg(xp + j * (Bb / 2));
        #pragma unroll
        for (int blk = 0; blk < 4; blk++) {
          float2 nbuf[8];
          if (blk < 3) {
            #pragma unroll
            for (int j = 0; j < 8; j++)
              nbuf[j] = __ldcg(xp + ((blk + 1) * 8 + j) * (Bb / 2));
          }
          #pragma unroll
          for (int j = 0; j < 8; j++) {
            int k = blk * 8 + j;
            ull x0b = bcast2(buf[j].x), x1b = bcast2(buf[j].y);
            ulonglong2 wA = *(const ulonglong2*)(wp + k * (NC2 / 2));
            asm("fma.rn.f32x2 %0, %1, %2, %0;" : "+l"(acc2[0]) : "l"(x0b), "l"(wA.x));
            asm("fma.rn.f32x2 %0, %1, %2, %0;" : "+l"(acc2[1]) : "l"(x0b), "l"(wA.y));
            asm("fma.rn.f32x2 %0, %1, %2, %0;" : "+l"(acc2[2]) : "l"(x1b), "l"(wA.x));
            asm("fma.rn.f32x2 %0, %1, %2, %0;" : "+l"(acc2[3]) : "l"(x1b), "l"(wA.y));
          }
          #pragma unroll
          for (int j = 0; j < 8; j++) buf[j] = nbuf[j];
        }
      }
      { // store partials, layout [ks][n][m], conflict-free
        float* rp = s_red + ks * (NC2 * Bb);
        #pragma unroll
        for (int p = 0; p < 2; p++) {
          float e0, o0, e1, o1;
          unpack2(acc2[p],     e0, o0);
          unpack2(acc2[2 + p], e1, o1);
          float2 ve; ve.x = e0; ve.y = e1;
          float2 vo; vo.x = o0; vo.y = o1;
          *(float2*)(rp + (2 * p)     * Bb + m0) = ve;
          *(float2*)(rp + (2 * p + 1) * Bb + m0) = vo;
        }
      }
      __syncthreads();

      if (tid < 256) {                  // 64 batch x 4 cols; conflict-free LDS
        int mm = tid & 63, n = tid >> 6;
        float s = s_b2[n];
        #pragma unroll
        for (int q = 0; q < NSL; q++) s += s_red[q * (NC2 * Bb) + n * Bb + mm];
        int c = cid * NC2 + n;
        float r  = tanhf(s);
        float z  = __ldcg(&g_z[c * Bb + mm]);
        float xo = __ldcg(&g_xT[c * Bb + mm]);
        g_xT[c * Bb + mm] = (1.0f - z) * xo + z * r;
      }
    }
    // ---- barrier 2: release (writers only) + arrive, overlap, wait ----
    if (cid < NCTA2 && tid < 256) __threadfence();
    __syncthreads();
    if (tid == 0) atomicAdd(&g_bar, 1u);
    target += NCTA1;

    // overlap: phase-1 u-segment for t+1 (clamped; last iter redundant)
    {
      int tn = (t + 1 < Tt) ? (t + 1) : (Tt - 1);
      const float2* up = (const float2*)(g_uT + (size_t)tn * (INx * Bb) + (ks * 4) * Bb + m0);
      const ull*    wp = (const ull*)(s_w1 + (Hh + ks * 4) * NC1);
      #pragma unroll
      for (int p = 0; p < 8; p++) acc1u[p] = 0ull;
      #pragma unroll
      for (int k = 0; k < 4; k++) {
        float2 xv = up[k * (Bb / 2)];
        ull x0b = bcast2(xv.x), x1b = bcast2(xv.y);
        const ulonglong2* wv = (const ulonglong2*)(wp + k * (NC1 / 2));
        ulonglong2 wA = wv[0], wB = wv[1];
        asm("fma.rn.f32x2 %0, %1, %2, %0;" : "+l"(acc1u[0]) : "l"(x0b), "l"(wA.x));
        asm("fma.rn.f32x2 %0, %1, %2, %0;" : "+l"(acc1u[1]) : "l"(x0b), "l"(wA.y));
        asm("fma.rn.f32x2 %0, %1, %2, %0;" : "+l"(acc1u[2]) : "l"(x0b), "l"(wB.x));
        asm("fma.rn.f32x2 %0, %1, %2, %0;" : "+l"(acc1u[3]) : "l"(x0b), "l"(wB.y));
        asm("fma.rn.f32x2 %0, %1, %2, %0;" : "+l"(acc1u[4]) : "l"(x1b), "l"(wA.x));
        asm("fma.rn.f32x2 %0, %1, %2, %0;" : "+l"(acc1u[5]) : "l"(x1b), "l"(wA.y));
        asm("fma.rn.f32x2 %0, %1, %2, %0;" : "+l"(acc1u[6]) : "l"(x1b), "l"(wB.x));
        asm("fma.rn.f32x2 %0, %1, %2, %0;" : "+l"(acc1u[7]) : "l"(x1b), "l"(wB.y));
      }
    }
    if (tid == 0) { while (bar_poll() < target) { } }
    __syncthreads();
  }
}

// Runs BEFORE gru_main each invocation: resets the barrier counter and keeps
// gru_main as ncu launch #6 (-s 5 -c 1).
__global__ void zero_bar_kernel() { g_bar = 0u; }

extern "C" void kernel_launch(void* const* d_in, const int* in_sizes, int n_in,
                              void* d_out, int out_size) {
  // Resolve inputs by UNIQUE element counts (immune to metadata ordering).
  const float *u = 0, *x0 = 0, *kernel_fz = 0, *bias_fz = 0,
              *kernel_r = 0, *bias_r = 0, *W_out = 0, *b_out = 0;
  for (int i = 0; i < n_in; i++) {
    const float* p = (const float*)d_in[i];
    switch (in_sizes[i]) {
      case 8388608: u         = p; break;  // 64*2048*64
      case 32768:   x0        = p; break;  // 64*1*512
      case 589824:  kernel_fz = p; break;  // 576*1024
      case 1024:    bias_fz   = p; break;
      case 294912:  kernel_r  = p; break;  // 576*512
      case 512:     bias_r    = p; break;
      case 16384:   W_out     = p; break;  // 32*512
      case 32:      b_out     = p; break;
      default: break;
    }
  }
  if (!u || !x0 || !kernel_fz || !bias_fz || !kernel_r || !bias_r || !W_out || !b_out) {
    u         = (const float*)d_in[0];
    x0        = (const float*)d_in[1];
    kernel_fz = (const float*)d_in[2];
    bias_fz   = (const float*)d_in[3];
    kernel_r  = (const float*)d_in[4];
    bias_r    = (const float*)d_in[5];
    W_out     = (const float*)d_in[6];
    b_out     = (const float*)d_in[7];
  }
  float* out = (float*)d_out;

  static int smem_set = 0;
  if (!smem_set) {
    cudaFuncSetAttribute(gru_main, cudaFuncAttributeMaxDynamicSharedMemorySize,
                         SMEM_BYTES);
    smem_set = 1;
  }

  zero_bar_kernel<<<1, 1>>>();

  void* args[] = { (void*)&u, (void*)&x0,
                   (void*)&kernel_fz, (void*)&bias_fz, (void*)&kernel_r,
                   (void*)&bias_r,    (void*)&W_out,   (void*)&b_out,
                   (void*)&out };
  cudaLaunchCooperativeKernel((const void*)gru_main, dim3(NCTA1), dim3(NTHR),
                              args, SMEM_BYTES, (cudaStream_t)0);
}

// round 12
// speedup vs baseline: 1.7214x; 1.0216x over previous
#include <cuda_runtime.h>
#include <math.h>
#include <stdint.h>

// Problem dims
#define Bb   64
#define Tt   2048
#define INx  64
#define Hh   512
#define OUTD 32
#define K1   576      // INx + Hh
#define NCTA 132      // 4 groups x 33 CTAs
#define GRP  4        // independent batch groups
#define CPG  33       // CTAs per group (32 p1-cols each; lc=32 = the 32 y cols)
#define BG   16       // batch rows per group
#define NC1g 32       // phase-1 cols per CTA
#define NC2g 16       // phase-2 cols per CTA (lc<32)
#define NTHR 512
#define NSL  16       // K-slices: 16 x (32 x-rows + 4 u-rows)

typedef unsigned long long ull;

// ---- persistent device scratch (no allocation allowed) ----
__device__ float g_xT [Hh * Bb];               // state, transposed [k][m]
__device__ float g_xfT[Hh * Bb];               // f*x, transposed  [k][m]
__device__ float g_z  [Hh * Bb];               // z gate           [j][m]
__device__ float g_uT [(size_t)Tt * INx * Bb]; // u transposed: [t][i][m]  (32 MB)
__device__ unsigned g_bar;                     // one-time global init barrier
__device__ unsigned g_barG[GRP * 32];          // per-group counters, 128B apart

// SMEM layout (floats) in dynamic shared memory
#define OFF_W1  0                    // 576*32 = 18432
#define OFF_W2  18432                // 576*16 =  9216
#define OFF_RED 27648                // 16*32*16 = 8192 (also transpose tile: 4160)
#define OFF_B1  35840                // 32
#define OFF_B2  35872                // 16
#define SMEM_FLOATS 35888
#define SMEM_BYTES  (SMEM_FLOATS * 4)

__device__ __forceinline__ ull bcast2(float v) {
  ull r;
  asm("mov.b64 %0, {%1, %1};" : "=l"(r) : "r"(__float_as_uint(v)));
  return r;
}
__device__ __forceinline__ unsigned poll_at(const unsigned* p) {
  unsigned v;
  asm volatile("ld.acquire.gpu.global.u32 %0, [%1];" : "=r"(v) : "l"(p) : "memory");
  return v;
}
__device__ __forceinline__ void unpack2(ull a, float& lo, float& hi) {
  unsigned l, h;
  asm("mov.b64 {%0,%1}, %2;" : "=r"(l), "=r"(h) : "l"(a));
  lo = __uint_as_float(l); hi = __uint_as_float(h);
}

__global__ void __launch_bounds__(NTHR, 1) gru_main(
    const float* __restrict__ u,
    const float* __restrict__ x0,
    const float* __restrict__ kernel_fz, const float* __restrict__ bias_fz,
    const float* __restrict__ kernel_r,  const float* __restrict__ bias_r,
    const float* __restrict__ W_out,     const float* __restrict__ b_out,
    float* __restrict__ out)
{
  extern __shared__ float smem[];
  float* s_w1  = smem + OFF_W1;   // [kk][32], kk 0..511 = x rows, 512..575 = u rows
  float* s_w2  = smem + OFF_W2;   // [kk][16]
  float* s_red = smem + OFF_RED;  // [ks][n][BG] — conflict-free
  float* s_b1  = smem + OFF_B1;
  float* s_b2  = smem + OFF_B2;

  const int tid = threadIdx.x;
  const int cid = blockIdx.x;
  const int grp = cid / CPG;          // batch group 0..3
  const int lc  = cid - grp * CPG;    // 0..32 within group
  const int gbase = grp * BG;         // first batch row of group
  const int mg  = tid & 7;            // m-pair within group (rows 2mg, 2mg+1)
  const int cs  = (tid >> 3) & 3;     // column split
  const int ks  = tid >> 5;           // K-slice 0..15
  const int m0  = 2 * mg;
  unsigned* barp = &g_barG[grp * 32];

  // ---- stationary weight slices into SMEM ----
  for (int i = tid; i < K1 * NC1g; i += NTHR) {
    int kk = i / NC1g, n = i % NC1g;
    int c  = lc * NC1g + n;
    int row = (kk < Hh) ? (INx + kk) : (kk - Hh);   // concat order: [u | x]
    float w;
    if (c < 2 * Hh) w = kernel_fz[row * (2 * Hh) + c];
    else { int o = c - 2 * Hh; w = (kk < Hh) ? W_out[o * Hh + kk] : 0.0f; }
    s_w1[i] = w;
  }
  if (lc < 32) {
    for (int i = tid; i < K1 * NC2g; i += NTHR) {
      int kk = i / NC2g, n = i % NC2g;
      int j  = lc * NC2g + n;
      int row = (kk < Hh) ? (INx + kk) : (kk - Hh);
      s_w2[i] = kernel_r[row * Hh + j];
    }
  }
  if (tid < NC1g) {
    int c = lc * NC1g + tid;
    s_b1[tid] = (c < 2 * Hh) ? bias_fz[c] : b_out[c - 2 * Hh];
  }
  if (lc < 32 && tid < NC2g) s_b2[tid] = bias_r[lc * NC2g + tid];

  // ---- in-kernel init: x0 -> g_xT (grid-stride) ----
  for (int idx = cid * NTHR + tid; idx < Hh * Bb; idx += NCTA * NTHR) {
    int k = idx >> 6, mm = idx & 63;
    g_xT[idx] = x0[mm * Hh + k];          // x0 is (64, 1, 512)
  }

  // ---- in-kernel u transpose: u(B,T,IN) -> g_uT[t][i][m] ----
  {
    float* tile = s_red;                  // 64*65 = 4160 floats fits in RED region
    __syncthreads();
    for (int t = cid; t < Tt; t += NCTA) {
      for (int idx = tid; idx < INx * Bb; idx += NTHR) {
        int mm = idx >> 6, i = idx & 63;
        tile[mm * 65 + i] = u[((size_t)mm * Tt + t) * INx + i];
      }
      __syncthreads();
      for (int idx = tid; idx < INx * Bb; idx += NTHR) {
        g_uT[(size_t)t * (INx * Bb) + idx] = tile[(idx & 63) * 65 + (idx >> 6)];
      }
      __syncthreads();
    }
  }

  // ---- one-time GLOBAL barrier after init/transpose ----
  __threadfence();
  __syncthreads();
  if (tid == 0) atomicAdd(&g_bar, 1u);
  if (tid == 0) { while (poll_at(&g_bar) < NCTA) { } }
  __syncthreads();

  // ---- prologue: phase-1 u-segment for t = 0 ----
  ull acc1u[8];    // [0..3] = m0 col-pairs(01,23,45,67 of cs*8), [4..7] = m1
  {
    #pragma unroll
    for (int p = 0; p < 8; p++) acc1u[p] = 0ull;
    const float2* up = (const float2*)(g_uT + (ks * 4) * Bb + gbase + m0);
    const float*  wp = s_w1 + (Hh + ks * 4) * NC1g + cs * 8;
    #pragma unroll
    for (int k = 0; k < 4; k++) {
      float2 xv = up[k * (Bb / 2)];
      ull x0b = bcast2(xv.x), x1b = bcast2(xv.y);
      const ulonglong2* wv = (const ulonglong2*)(wp + k * NC1g);
      ulonglong2 wA = wv[0], wB = wv[1];
      asm("fma.rn.f32x2 %0, %1, %2, %0;" : "+l"(acc1u[0]) : "l"(x0b), "l"(wA.x));
      asm("fma.rn.f32x2 %0, %1, %2, %0;" : "+l"(acc1u[1]) : "l"(x0b), "l"(wA.y));
      asm("fma.rn.f32x2 %0, %1, %2, %0;" : "+l"(acc1u[2]) : "l"(x0b), "l"(wB.x));
      asm("fma.rn.f32x2 %0, %1, %2, %0;" : "+l"(acc1u[3]) : "l"(x0b), "l"(wB.y));
      asm("fma.rn.f32x2 %0, %1, %2, %0;" : "+l"(acc1u[4]) : "l"(x1b), "l"(wA.x));
      asm("fma.rn.f32x2 %0, %1, %2, %0;" : "+l"(acc1u[5]) : "l"(x1b), "l"(wA.y));
      asm("fma.rn.f32x2 %0, %1, %2, %0;" : "+l"(acc1u[6]) : "l"(x1b), "l"(wB.x));
      asm("fma.rn.f32x2 %0, %1, %2, %0;" : "+l"(acc1u[7]) : "l"(x1b), "l"(wB.y));
    }
  }

  unsigned tg = 0;
  for (int t = 0; t < Tt; t++) {
    const float* uT_t = g_uT + (size_t)t * (INx * Bb);

    // ================= phase 1: fz logits + y readout =================
    {
      ull acc[8];
      #pragma unroll
      for (int p = 0; p < 8; p++) acc[p] = acc1u[p];

      { // x segment: rows [ks*32, ks*32+32), register staging
        const float2* xp = (const float2*)(g_xT + (ks * 32) * Bb + gbase + m0);
        const float*  wp = s_w1 + (ks * 32) * NC1g + cs * 8;
        float2 buf[8];
        #pragma unroll
        for (int j = 0; j < 8; j++) buf[j] = __ldcg(xp + j * (Bb / 2));
        #pragma unroll
        for (int blk = 0; blk < 4; blk++) {
          float2 nbuf[8];
          if (blk < 3) {
            #pragma unroll
            for (int j = 0; j < 8; j++)
              nbuf[j] = __ldcg(xp + ((blk + 1) * 8 + j) * (Bb / 2));
          }
          #pragma unroll
          for (int j = 0; j < 8; j++) {
            int k = blk * 8 + j;
            ull x0b = bcast2(buf[j].x), x1b = bcast2(buf[j].y);
            const ulonglong2* wv = (const ulonglong2*)(wp + k * NC1g);
            ulonglong2 wA = wv[0], wB = wv[1];
            asm("fma.rn.f32x2 %0, %1, %2, %0;" : "+l"(acc[0]) : "l"(x0b), "l"(wA.x));
            asm("fma.rn.f32x2 %0, %1, %2, %0;" : "+l"(acc[1]) : "l"(x0b), "l"(wA.y));
            asm("fma.rn.f32x2 %0, %1, %2, %0;" : "+l"(acc[2]) : "l"(x0b), "l"(wB.x));
            asm("fma.rn.f32x2 %0, %1, %2, %0;" : "+l"(acc[3]) : "l"(x0b), "l"(wB.y));
            asm("fma.rn.f32x2 %0, %1, %2, %0;" : "+l"(acc[4]) : "l"(x1b), "l"(wA.x));
            asm("fma.rn.f32x2 %0, %1, %2, %0;" : "+l"(acc[5]) : "l"(x1b), "l"(wA.y));
            asm("fma.rn.f32x2 %0, %1, %2, %0;" : "+l"(acc[6]) : "l"(x1b), "l"(wB.x));
            asm("fma.rn.f32x2 %0, %1, %2, %0;" : "+l"(acc[7]) : "l"(x1b), "l"(wB.y));
          }
          #pragma unroll
          for (int j = 0; j < 8; j++) buf[j] = nbuf[j];
        }
      }
      { // store partials, layout [ks][n][BG]: float2(m0,m1) per column — conflict-free
        float* rp = s_red + ks * (NC1g * BG);
        int colb = cs * 8;
        #pragma unroll
        for (int p = 0; p < 4; p++) {
          float e0, o0, e1, o1;
          unpack2(acc[p],     e0, o0);
          unpack2(acc[4 + p], e1, o1);
          float2 ve; ve.x = e0; ve.y = e1;
          float2 vo; vo.x = o0; vo.y = o1;
          *(float2*)(rp + (colb + 2 * p)     * BG + m0) = ve;
          *(float2*)(rp + (colb + 2 * p + 1) * BG + m0) = vo;
        }
      }
      __syncthreads();

      { // epilogue: 512 threads -> 16 batch x 32 cols
        int mm = tid & 15, n = tid >> 4;       // n 0..31
        float s = s_b1[n];
        #pragma unroll
        for (int q = 0; q < NSL; q++) s += s_red[q * (NC1g * BG) + n * BG + mm];
        int c   = lc * NC1g + n;
        int mgl = gbase + mm;
        if (c < Hh) {                                  // f gate -> f*x
          float f  = 1.0f / (1.0f + expf(-s));
          g_xfT[c * Bb + mgl] = f * __ldcg(&g_xT[c * Bb + mgl]);
        } else if (c < 2 * Hh) {                       // z gate
          g_z[(c - Hh) * Bb + mgl] = 1.0f / (1.0f + expf(-s));
        } else {                                       // y readout (pre-update x)
          out[((size_t)mgl * Tt + t) * OUTD + (c - 2 * Hh)] = s;
        }
      }
    }
    // ---- group barrier 1: release (writers only) + arrive, overlap, wait ----
    if (lc < 32) __threadfence();          // lc==32 wrote only `out`
    __syncthreads();
    if (tid == 0) atomicAdd(barp, 1u);
    tg += CPG;

    // overlap: phase-2 u-segment (depends only on g_uT)
    ull acc2[4] = {0ull, 0ull, 0ull, 0ull}; // [0..1] m0 pairs(01,23 of cs*4), [2..3] m1
    if (lc < 32) {
      const float2* up = (const float2*)(uT_t + (ks * 4) * Bb + gbase + m0);
      const float*  wp = s_w2 + (Hh + ks * 4) * NC2g + cs * 4;
      #pragma unroll
      for (int k = 0; k < 4; k++) {
        float2 xv = up[k * (Bb / 2)];
        ull x0b = bcast2(xv.x), x1b = bcast2(xv.y);
        ulonglong2 wA = *(const ulonglong2*)(wp + k * NC2g);
        asm("fma.rn.f32x2 %0, %1, %2, %0;" : "+l"(acc2[0]) : "l"(x0b), "l"(wA.x));
        asm("fma.rn.f32x2 %0, %1, %2, %0;" : "+l"(acc2[1]) : "l"(x0b), "l"(wA.y));
        asm("fma.rn.f32x2 %0, %1, %2, %0;" : "+l"(acc2[2]) : "l"(x1b), "l"(wA.x));
        asm("fma.rn.f32x2 %0, %1, %2, %0;" : "+l"(acc2[3]) : "l"(x1b), "l"(wA.y));
      }
    }
    if (tid == 0) { while (poll_at(barp) < tg) { } }
    __syncthreads();

    // ================= phase 2: r + state update =================
    if (lc < 32) {
      { // x segment with register staging
        const float2* xp = (const float2*)(g_xfT + (ks * 32) * Bb + gbase + m0);
        const float*  wp = s_w2 + (ks * 32) * NC2g + cs * 4;
        float2 buf[8];
        #pragma unroll
        for (int j = 0; j < 8; j++) buf[j] = __ldcg(xp + j * (Bb / 2));
        #pragma unroll
        for (int blk = 0; blk < 4; blk++) {
          float2 nbuf[8];
          if (blk < 3) {
            #pragma unroll
            for (int j = 0; j < 8; j++)
              nbuf[j] = __ldcg(xp + ((blk + 1) * 8 + j) * (Bb / 2));
          }
          #pragma unroll
          for (int j = 0; j < 8; j++) {
            int k = blk * 8 + j;
            ull x0b = bcast2(buf[j].x), x1b = bcast2(buf[j].y);
            ulonglong2 wA = *(const ulonglong2*)(wp + k * NC2g);
            asm("fma.rn.f32x2 %0, %1, %2, %0;" : "+l"(acc2[0]) : "l"(x0b), "l"(wA.x));
            asm("fma.rn.f32x2 %0, %1, %2, %0;" : "+l"(acc2[1]) : "l"(x0b), "l"(wA.y));
            asm("fma.rn.f32x2 %0, %1, %2, %0;" : "+l"(acc2[2]) : "l"(x1b), "l"(wA.x));
            asm("fma.rn.f32x2 %0, %1, %2, %0;" : "+l"(acc2[3]) : "l"(x1b), "l"(wA.y));
          }
          #pragma unroll
          for (int j = 0; j < 8; j++) buf[j] = nbuf[j];
        }
      }
      { // store partials, layout [ks][n][BG], conflict-free
        float* rp = s_red + ks * (NC2g * BG);
        int colb = cs * 4;
        #pragma unroll
        for (int p = 0; p < 2; p++) {
          float e0, o0, e1, o1;
          unpack2(acc2[p],     e0, o0);
          unpack2(acc2[2 + p], e1, o1);
          float2 ve; ve.x = e0; ve.y = e1;
          float2 vo; vo.x = o0; vo.y = o1;
          *(float2*)(rp + (colb + 2 * p)     * BG + m0) = ve;
          *(float2*)(rp + (colb + 2 * p + 1) * BG + m0) = vo;
        }
      }
      __syncthreads();

      if (tid < 256) {                  // 16 batch x 16 cols
        int mm = tid & 15, n = tid >> 4;     // n 0..15
        float s = s_b2[n];
        #pragma unroll
        for (int q = 0; q < NSL; q++) s += s_red[q * (NC2g * BG) + n * BG + mm];
        int j   = lc * NC2g + n;
        int mgl = gbase + mm;
        float r  = tanhf(s);
        float z  = __ldcg(&g_z[j * Bb + mgl]);
        float xo = __ldcg(&g_xT[j * Bb + mgl]);
        g_xT[j * Bb + mgl] = (1.0f - z) * xo + z * r;
      }
    }
    // ---- group barrier 2: release (writers only) + arrive, overlap, wait ----
    if (lc < 32 && tid < 256) __threadfence();
    __syncthreads();
    if (tid == 0) atomicAdd(barp, 1u);
    tg += CPG;

    // overlap: phase-1 u-segment for t+1 (clamped; last iter redundant)
    {
      int tn = (t + 1 < Tt) ? (t + 1) : (Tt - 1);
      const float2* up = (const float2*)(g_uT + (size_t)tn * (INx * Bb) + (ks * 4) * Bb + gbase + m0);
      const float*  wp = s_w1 + (Hh + ks * 4) * NC1g + cs * 8;
      #pragma unroll
      for (int p = 0; p < 8; p++) acc1u[p] = 0ull;
      #pragma unroll
      for (int k = 0; k < 4; k++) {
        float2 xv = up[k * (Bb / 2)];
        ull x0b = bcast2(xv.x), x1b = bcast2(xv.y);
        const ulonglong2* wv = (const ulonglong2*)(wp + k * NC1g);
        ulonglong2 wA = wv[0], wB = wv[1];
        asm("fma.rn.f32x2 %0, %1, %2, %0;" : "+l"(acc1u[0]) : "l"(x0b), "l"(wA.x));
        asm("fma.rn.f32x2 %0, %1, %2, %0;" : "+l"(acc1u[1]) : "l"(x0b), "l"(wA.y));
        asm("fma.rn.f32x2 %0, %1, %2, %0;" : "+l"(acc1u[2]) : "l"(x0b), "l"(wB.x));
        asm("fma.rn.f32x2 %0, %1, %2, %0;" : "+l"(acc1u[3]) : "l"(x0b), "l"(wB.y));
        asm("fma.rn.f32x2 %0, %1, %2, %0;" : "+l"(acc1u[4]) : "l"(x1b), "l"(wA.x));
        asm("fma.rn.f32x2 %0, %1, %2, %0;" : "+l"(acc1u[5]) : "l"(x1b), "l"(wA.y));
        asm("fma.rn.f32x2 %0, %1, %2, %0;" : "+l"(acc1u[6]) : "l"(x1b), "l"(wB.x));
        asm("fma.rn.f32x2 %0, %1, %2, %0;" : "+l"(acc1u[7]) : "l"(x1b), "l"(wB.y));
      }
    }
    if (tid == 0) { while (poll_at(barp) < tg) { } }
    __syncthreads();
  }
}

// Runs BEFORE gru_main each invocation: resets all barrier counters and keeps
// gru_main as ncu launch #6 (-s 5 -c 1).
__global__ void zero_bar_kernel() {
  g_bar = 0u;
  for (int g = 0; g < GRP; g++) g_barG[g * 32] = 0u;
}

extern "C" void kernel_launch(void* const* d_in, const int* in_sizes, int n_in,
                              void* d_out, int out_size) {
  // Resolve inputs by UNIQUE element counts (immune to metadata ordering).
  const float *u = 0, *x0 = 0, *kernel_fz = 0, *bias_fz = 0,
              *kernel_r = 0, *bias_r = 0, *W_out = 0, *b_out = 0;
  for (int i = 0; i < n_in; i++) {
    const float* p = (const float*)d_in[i];
    switch (in_sizes[i]) {
      case 8388608: u         = p; break;  // 64*2048*64
      case 32768:   x0        = p; break;  // 64*1*512
      case 589824:  kernel_fz = p; break;  // 576*1024
      case 1024:    bias_fz   = p; break;
      case 294912:  kernel_r  = p; break;  // 576*512
      case 512:     bias_r    = p; break;
      case 16384:   W_out     = p; break;  // 32*512
      case 32:      b_out     = p; break;
      default: break;
    }
  }
  if (!u || !x0 || !kernel_fz || !bias_fz || !kernel_r || !bias_r || !W_out || !b_out) {
    u         = (const float*)d_in[0];
    x0        = (const float*)d_in[1];
    kernel_fz = (const float*)d_in[2];
    bias_fz   = (const float*)d_in[3];
    kernel_r  = (const float*)d_in[4];
    bias_r    = (const float*)d_in[5];
    W_out     = (const float*)d_in[6];
    b_out     = (const float*)d_in[7];
  }
  float* out = (float*)d_out;

  static int smem_set = 0;
  if (!smem_set) {
    cudaFuncSetAttribute(gru_main, cudaFuncAttributeMaxDynamicSharedMemorySize,
                         SMEM_BYTES);
    smem_set = 1;
  }

  zero_bar_kernel<<<1, 1>>>();

  void* args[] = { (void*)&u, (void*)&x0,
                   (void*)&kernel_fz, (void*)&bias_fz, (void*)&kernel_r,
                   (void*)&bias_r,    (void*)&W_out,   (void*)&b_out,
                   (void*)&out };
  cudaLaunchCooperativeKernel((const void*)gru_main, dim3(NCTA), dim3(NTHR),
                              args, SMEM_BYTES, (cudaStream_t)0);
}